// round 1
// baseline (speedup 1.0000x reference)
#include <cuda_runtime.h>
#include <cuda_bf16.h>
#include <math_constants.h>

// ---------------------------------------------------------------------------
// Problem shapes
//   x:   [512, 4, 10, 2] int32
//   t:   [512, 4, 128, 128] f32 (rasterized)
//   c1:  conv 7x7 s2 p3, 4->32   -> [512,32,64,64], relu
//   p1:  maxpool 3x3 s2          -> [512,32,31,31]
//   c2:  conv 5x5 s1 p2, 32->64  -> [512,64,31,31], relu
//   p2:  maxpool 2x2 s2          -> [512,64,15,15]
//   c3:  conv 3x3 s1 p1, 64->128 -> [512,128,15,15], relu
//   p3+avg: maxpool 2x2 s2 -> [7,7], mean -> [512,128]
//   fc1: 128->128 relu, fc2: 128->5 -> out [512,5] f32
// ---------------------------------------------------------------------------

#define NB 512
#define NF 4
#define NIMG (NB * NF)   // 2048

// Scratch (device globals; no allocation allowed)
__device__ float g_t  [NIMG * 128 * 128];        // 33.5M
__device__ float g_c1 [NB * 32 * 64 * 64];       // 67.1M
__device__ float g_p1 [NB * 32 * 31 * 31];       // 15.7M
__device__ float g_c2 [NB * 64 * 31 * 31];       // 31.5M
__device__ float g_p2 [NB * 64 * 15 * 15];       // 7.4M
__device__ float g_c3 [NB * 128 * 15 * 15];      // 14.7M
__device__ float g_avg[NB * 128];

// ---------------------------------------------------------------------------
// Rasterize. One block per (b,f) image.
// ---------------------------------------------------------------------------
__global__ void k_raster(const int* __restrict__ x) {
    int img = blockIdx.x;              // b*4 + f
    __shared__ int ax[9], ay[9];
    __shared__ int sdX, sloX, shiX, sloY, shiY;
    int tid = threadIdx.x;
    if (tid < 9) {
        int vx = x[img * 20 + tid * 2 + 0];
        int vy = x[img * 20 + tid * 2 + 1];
        int a = ((vx + 64) % 127 + 127) % 127;
        int b = ((64 - vy) % 127 + 127) % 127;
        ax[tid] = a; ay[tid] = b;
    }
    if (tid == 9) {
        int vx = x[img * 20 + 18];
        int vy = x[img * 20 + 19];
        int dX = 64 + vx, dY = 64 - vy;
        sdX = dX;
        sloX = (dX >= 64) ? 64 : dX + 1;
        shiX = (dX >= 64) ? dX - 1 : 64;
        sloY = (dY >= 64) ? 64 : dY + 1;
        shiY = (dY >= 64) ? dY - 1 : 64;
    }
    __syncthreads();
    float* out = g_t + (size_t)img * 16384;
    for (int p = tid; p < 16384; p += blockDim.x) {
        int y = p >> 7, xx = p & 127;
        float val = 0.f;
        if (y == 64 && xx >= sloX && xx <= shiX) val = -1.f;
        if (xx == sdX && y >= sloY && y <= shiY) val = -1.f;
        if (y >= 63 && y <= 65 && xx >= 63 && xx <= 65)
            val = (y == 64 && xx == 64) ? 1.f : 0.5f;
        #pragma unroll
        for (int k = 0; k < 9; k++) {
            int dy = y - ay[k], dx = xx - ax[k];
            if (dy >= -1 && dy <= 1 && dx >= -1 && dx <= 1)
                val = (dy == 0 && dx == 0) ? 1.f : 0.5f;
        }
        out[p] = val;
    }
}

// ---------------------------------------------------------------------------
// Conv1: 7x7 s2 p3, 4->32, + bias + relu.  grid (512, 16), block 256.
// Tile = 16x16 output pixels. Each thread: 1 pixel x 32 oc.
// ---------------------------------------------------------------------------
__global__ __launch_bounds__(256, 1) void k_conv1(const float* __restrict__ w1,
                                                  const float* __restrict__ b1) {
    __shared__ float sW[4 * 49 * 32];      // [ci][ky][kx][oc], 25088 B
    __shared__ float sIn[4][37][38];       // 22496 B
    int b    = blockIdx.x;
    int tile = blockIdx.y;
    int y0 = (tile >> 2) * 16, x0 = (tile & 3) * 16;
    int tid = threadIdx.x;

    for (int i = tid; i < 6272; i += 256) {
        int oc = i & 31; int r = i >> 5;
        int kx = r % 7; int q = r / 7; int ky = q % 7; int ci = q / 7;
        sW[i] = w1[((oc * 4 + ci) * 7 + ky) * 7 + kx];
    }
    int iy0 = 2 * y0 - 3, ix0 = 2 * x0 - 3;
    for (int i = tid; i < 4 * 37 * 37; i += 256) {
        int ci = i / (37 * 37); int r = (i / 37) % 37; int c = i % 37;
        int gy = iy0 + r, gx = ix0 + c;
        float v = 0.f;
        if (gy >= 0 && gy < 128 && gx >= 0 && gx < 128)
            v = g_t[((size_t)(b * 4 + ci) * 128 + gy) * 128 + gx];
        sIn[ci][r][c] = v;
    }
    __syncthreads();

    int ty = tid >> 4, tx = tid & 15;
    float acc[32];
    #pragma unroll
    for (int j = 0; j < 32; j++) acc[j] = 0.f;

    for (int ci = 0; ci < 4; ci++)
        for (int ky = 0; ky < 7; ky++)
            #pragma unroll
            for (int kx = 0; kx < 7; kx++) {
                float v = sIn[ci][2 * ty + ky][2 * tx + kx];
                const float4* wp = (const float4*)&sW[((ci * 7 + ky) * 7 + kx) * 32];
                #pragma unroll
                for (int j = 0; j < 8; j++) {
                    float4 w = wp[j];
                    acc[4 * j + 0] += v * w.x;
                    acc[4 * j + 1] += v * w.y;
                    acc[4 * j + 2] += v * w.z;
                    acc[4 * j + 3] += v * w.w;
                }
            }

    int oy = y0 + ty, ox = x0 + tx;
    float* op = g_c1 + (size_t)b * 32 * 4096 + oy * 64 + ox;
    #pragma unroll
    for (int oc = 0; oc < 32; oc++) {
        float vv = acc[oc] + b1[oc];
        op[(size_t)oc * 4096] = vv > 0.f ? vv : 0.f;
    }
}

// ---------------------------------------------------------------------------
// Pool1: 3x3 s2 on [*,32,64,64] -> [*,32,31,31]
// ---------------------------------------------------------------------------
__global__ void k_pool1() {
    int idx = blockIdx.x * blockDim.x + threadIdx.x;
    const int total = NB * 32 * 31 * 31;
    if (idx >= total) return;
    int px = idx % 31; int r = idx / 31;
    int py = r % 31;   int c = r / 31;   // c = b*32 + oc
    const float* ip = g_c1 + (size_t)c * 4096 + (2 * py) * 64 + 2 * px;
    float m = -CUDART_INF_F;
    #pragma unroll
    for (int dy = 0; dy < 3; dy++)
        #pragma unroll
        for (int dx = 0; dx < 3; dx++)
            m = fmaxf(m, ip[dy * 64 + dx]);
    g_p1[idx] = m;
}

// ---------------------------------------------------------------------------
// Conv2: 5x5 s1 p2, 32->64, + bias + relu. grid (512, 4), block 256.
// Tile 16x16 over 31x31. Thread: 1 px x 64 oc. ci chunked by 4.
// ---------------------------------------------------------------------------
__global__ __launch_bounds__(256, 1) void k_conv2(const float* __restrict__ w2,
                                                  const float* __restrict__ b2) {
    __shared__ float sW[4 * 25 * 64];   // [ci][ky][kx][oc], 25600 B
    __shared__ float sIn[4][20][20];    // 6400 B
    int b    = blockIdx.x;
    int tile = blockIdx.y;
    int y0 = (tile >> 1) * 16, x0 = (tile & 1) * 16;
    int tid = threadIdx.x;
    int ty = tid >> 4, tx = tid & 15;

    float acc[64];
    #pragma unroll
    for (int j = 0; j < 64; j++) acc[j] = 0.f;

    for (int c0 = 0; c0 < 32; c0 += 4) {
        __syncthreads();
        for (int i = tid; i < 4 * 25 * 64; i += 256) {
            int oc = i & 63; int r = i >> 6;
            int kx = r % 5; int q = r / 5; int ky = q % 5; int ci = q / 5;
            sW[i] = w2[(((size_t)oc * 32 + c0 + ci) * 5 + ky) * 5 + kx];
        }
        for (int i = tid; i < 4 * 20 * 20; i += 256) {
            int ci = i / 400; int rr = (i / 20) % 20; int cc = i % 20;
            int gy = y0 - 2 + rr, gx = x0 - 2 + cc;
            float v = 0.f;
            if (gy >= 0 && gy < 31 && gx >= 0 && gx < 31)
                v = g_p1[((size_t)(b * 32 + c0 + ci) * 31 + gy) * 31 + gx];
            sIn[ci][rr][cc] = v;
        }
        __syncthreads();
        for (int ci = 0; ci < 4; ci++)
            for (int ky = 0; ky < 5; ky++)
                #pragma unroll
                for (int kx = 0; kx < 5; kx++) {
                    float v = sIn[ci][ty + ky][tx + kx];
                    const float4* wp = (const float4*)&sW[((ci * 5 + ky) * 5 + kx) * 64];
                    #pragma unroll
                    for (int j = 0; j < 16; j++) {
                        float4 w = wp[j];
                        acc[4 * j + 0] += v * w.x;
                        acc[4 * j + 1] += v * w.y;
                        acc[4 * j + 2] += v * w.z;
                        acc[4 * j + 3] += v * w.w;
                    }
                }
    }

    int oy = y0 + ty, ox = x0 + tx;
    if (oy < 31 && ox < 31) {
        float* op = g_c2 + (size_t)b * 64 * 961 + oy * 31 + ox;
        #pragma unroll
        for (int oc = 0; oc < 64; oc++) {
            float vv = acc[oc] + b2[oc];
            op[(size_t)oc * 961] = vv > 0.f ? vv : 0.f;
        }
    }
}

// ---------------------------------------------------------------------------
// Pool2: 2x2 s2 on [*,64,31,31] -> [*,64,15,15]
// ---------------------------------------------------------------------------
__global__ void k_pool2() {
    int idx = blockIdx.x * blockDim.x + threadIdx.x;
    const int total = NB * 64 * 15 * 15;
    if (idx >= total) return;
    int px = idx % 15; int r = idx / 15;
    int py = r % 15;   int c = r / 15;   // c = b*64 + oc
    const float* ip = g_c2 + (size_t)c * 961 + (2 * py) * 31 + 2 * px;
    float m = fmaxf(fmaxf(ip[0], ip[1]), fmaxf(ip[31], ip[32]));
    g_p2[idx] = m;
}

// ---------------------------------------------------------------------------
// Conv3: 3x3 s1 p1, 64->128, + bias + relu. grid (512, 2), block 256.
// Whole 15x15 image, 64 oc per block (blockIdx.y selects oc half).
// ---------------------------------------------------------------------------
__global__ __launch_bounds__(256, 1) void k_conv3(const float* __restrict__ w3,
                                                  const float* __restrict__ b3) {
    __shared__ float sW[8 * 9 * 64];    // [ci][ky][kx][oc], 18432 B
    __shared__ float sIn[8][17][17];    // 9248 B
    int b   = blockIdx.x;
    int oc0 = blockIdx.y * 64;
    int tid = threadIdx.x;

    float acc[64];
    #pragma unroll
    for (int j = 0; j < 64; j++) acc[j] = 0.f;
    int ty = tid / 15, tx = tid % 15;   // valid when tid < 225

    for (int c0 = 0; c0 < 64; c0 += 8) {
        __syncthreads();
        for (int i = tid; i < 8 * 9 * 64; i += 256) {
            int oc = i & 63; int r = i >> 6;
            int kx = r % 3; int q = r / 3; int ky = q % 3; int ci = q / 3;
            sW[i] = w3[(((size_t)(oc0 + oc) * 64 + c0 + ci) * 3 + ky) * 3 + kx];
        }
        for (int i = tid; i < 8 * 17 * 17; i += 256) {
            int ci = i / 289; int rr = (i / 17) % 17; int cc = i % 17;
            int gy = rr - 1, gx = cc - 1;
            float v = 0.f;
            if (gy >= 0 && gy < 15 && gx >= 0 && gx < 15)
                v = g_p2[((size_t)(b * 64 + c0 + ci) * 15 + gy) * 15 + gx];
            sIn[ci][rr][cc] = v;
        }
        __syncthreads();
        if (tid < 225) {
            for (int ci = 0; ci < 8; ci++)
                #pragma unroll
                for (int ky = 0; ky < 3; ky++)
                    #pragma unroll
                    for (int kx = 0; kx < 3; kx++) {
                        float v = sIn[ci][ty + ky][tx + kx];
                        const float4* wp = (const float4*)&sW[((ci * 9 + ky * 3 + kx)) * 64];
                        #pragma unroll
                        for (int j = 0; j < 16; j++) {
                            float4 w = wp[j];
                            acc[4 * j + 0] += v * w.x;
                            acc[4 * j + 1] += v * w.y;
                            acc[4 * j + 2] += v * w.z;
                            acc[4 * j + 3] += v * w.w;
                        }
                    }
        }
    }

    if (tid < 225) {
        float* op = g_c3 + (size_t)(b * 128 + oc0) * 225 + tid;
        #pragma unroll
        for (int oc = 0; oc < 64; oc++) {
            float vv = acc[oc] + b3[oc0 + oc];
            op[(size_t)oc * 225] = vv > 0.f ? vv : 0.f;
        }
    }
}

// ---------------------------------------------------------------------------
// Pool3 (2x2 s2: 15->7) + global mean over 7x7. Thread per (b,oc).
// ---------------------------------------------------------------------------
__global__ void k_avg() {
    int idx = blockIdx.x * blockDim.x + threadIdx.x;   // b*128 + oc
    if (idx >= NB * 128) return;
    const float* ip = g_c3 + (size_t)idx * 225;
    float s = 0.f;
    #pragma unroll
    for (int py = 0; py < 7; py++)
        #pragma unroll
        for (int px = 0; px < 7; px++) {
            const float* w = ip + (2 * py) * 15 + 2 * px;
            float m = fmaxf(fmaxf(w[0], w[1]), fmaxf(w[15], w[16]));
            s += m;
        }
    g_avg[idx] = s * (1.f / 49.f);
}

// ---------------------------------------------------------------------------
// FC: 128 -> 128 (relu) -> 5. Block per b, 128 threads.
// ---------------------------------------------------------------------------
__global__ void k_fc(const float* __restrict__ fw1, const float* __restrict__ fb1,
                     const float* __restrict__ fw2, const float* __restrict__ fb2,
                     float* __restrict__ out) {
    int b = blockIdx.x;
    int tid = threadIdx.x;
    __shared__ float sa[128], sh[128];
    sa[tid] = g_avg[b * 128 + tid];
    __syncthreads();
    float s = fb1[tid];
    const float* wr = fw1 + tid * 128;
    #pragma unroll 8
    for (int j = 0; j < 128; j++) s += wr[j] * sa[j];
    sh[tid] = s > 0.f ? s : 0.f;
    __syncthreads();
    if (tid < 5) {
        float o = fb2[tid];
        const float* wr2 = fw2 + tid * 128;
        #pragma unroll 8
        for (int j = 0; j < 128; j++) o += wr2[j] * sh[j];
        out[b * 5 + tid] = o;
    }
}

// ---------------------------------------------------------------------------
extern "C" void kernel_launch(void* const* d_in, const int* in_sizes, int n_in,
                              void* d_out, int out_size) {
    const int*   x   = (const int*)  d_in[0];
    const float* w1  = (const float*)d_in[1];
    const float* b1  = (const float*)d_in[2];
    const float* w2  = (const float*)d_in[3];
    const float* b2  = (const float*)d_in[4];
    const float* w3  = (const float*)d_in[5];
    const float* b3  = (const float*)d_in[6];
    const float* fw1 = (const float*)d_in[7];
    const float* fb1 = (const float*)d_in[8];
    const float* fw2 = (const float*)d_in[9];
    const float* fb2 = (const float*)d_in[10];
    float* out = (float*)d_out;

    k_raster<<<NIMG, 256>>>(x);
    k_conv1<<<dim3(NB, 16), 256>>>(w1, b1);
    {
        const int total = NB * 32 * 31 * 31;
        k_pool1<<<(total + 255) / 256, 256>>>();
    }
    k_conv2<<<dim3(NB, 4), 256>>>(w2, b2);
    {
        const int total = NB * 64 * 15 * 15;
        k_pool2<<<(total + 255) / 256, 256>>>();
    }
    k_conv3<<<dim3(NB, 2), 256>>>(w3, b3);
    k_avg<<<(NB * 128 + 255) / 256, 256>>>();
    k_fc<<<NB, 128>>>(fw1, fb1, fw2, fb2, out);
}

// round 2
// speedup vs baseline: 1.9630x; 1.9630x over previous
#include <cuda_runtime.h>
#include <cuda_bf16.h>
#include <math_constants.h>

// ---------------------------------------------------------------------------
// Pipeline (all activations NHWC):
//   x [512,4,10,2] i32 -> nonzero list (rasterized image is ~120/16384 nonzero)
//   conv1 7x7 s2 p3 4->32 : SPARSE scatter-add into c1 [512,64,64,32]
//   pool1 3x3 s2 (+bias+relu)        -> p1 [512,31,31,32]
//   conv2 5x5 s1 p2 32->64 (+relu)   -> c2 [512,31,31,64]
//   pool2 2x2 s2                     -> p2 [512,15,15,64]
//   conv3 3x3 s1 p1 64->128 (+relu)  -> c3 [512,225,128]
//   pool 2x2 s2 + mean               -> avg [512,128]
//   fc 128->128 relu -> 5            -> out [512,5]
// ---------------------------------------------------------------------------

#define NB 512
#define NIMG (NB * 4)

__device__ float g_c1 [NB * 64 * 64 * 32];       // NHWC, 67.1M floats
__device__ float g_p1 [NB * 31 * 31 * 32];       // NHWC
__device__ float g_c2 [NB * 31 * 31 * 64];       // NHWC
__device__ float g_p2 [NB * 15 * 15 * 64];       // NHWC
__device__ float g_c3 [NB * 225 * 128];          // [b][p<225][oc]
__device__ float g_avg[NB * 128];
__device__ int            g_nzcnt [NIMG];
__device__ unsigned short g_nzlist[NIMG * 256];

// ---------------------------------------------------------------------------
// Rasterize directly to a nonzero list. One block per (b,f) plane.
// Entry: p (14 bits) | code<<14, code: 0=0.5, 1=1.0, 2=-1.0
// ---------------------------------------------------------------------------
__global__ void k_raster_nz(const int* __restrict__ x) {
    int img = blockIdx.x;
    __shared__ int ax[9], ay[9];
    __shared__ int sdX, sloX, shiX, sloY, shiY;
    __shared__ int sCnt;
    __shared__ unsigned short sList[256];
    int tid = threadIdx.x;
    if (tid < 9) {
        int vx = x[img * 20 + tid * 2 + 0];
        int vy = x[img * 20 + tid * 2 + 1];
        ax[tid] = ((vx + 64) % 127 + 127) % 127;
        ay[tid] = ((64 - vy) % 127 + 127) % 127;
    }
    if (tid == 9) {
        int vx = x[img * 20 + 18];
        int vy = x[img * 20 + 19];
        int dX = 64 + vx, dY = 64 - vy;
        sdX = dX;
        sloX = (dX >= 64) ? 64 : dX + 1;
        shiX = (dX >= 64) ? dX - 1 : 64;
        sloY = (dY >= 64) ? 64 : dY + 1;
        shiY = (dY >= 64) ? dY - 1 : 64;
    }
    if (tid == 10) sCnt = 0;
    __syncthreads();
    for (int p = tid; p < 16384; p += blockDim.x) {
        int y = p >> 7, xx = p & 127;
        float val = 0.f;
        if (y == 64 && xx >= sloX && xx <= shiX) val = -1.f;
        if (xx == sdX && y >= sloY && y <= shiY) val = -1.f;
        if (y >= 63 && y <= 65 && xx >= 63 && xx <= 65)
            val = (y == 64 && xx == 64) ? 1.f : 0.5f;
        #pragma unroll
        for (int k = 0; k < 9; k++) {
            int dy = y - ay[k], dx = xx - ax[k];
            if (dy >= -1 && dy <= 1 && dx >= -1 && dx <= 1)
                val = (dy == 0 && dx == 0) ? 1.f : 0.5f;
        }
        if (val != 0.f) {
            int pos = atomicAdd(&sCnt, 1);
            if (pos < 256) {
                int code = (val == 0.5f) ? 0 : ((val == 1.f) ? 1 : 2);
                sList[pos] = (unsigned short)(p | (code << 14));
            }
        }
    }
    __syncthreads();
    int cnt = sCnt < 256 ? sCnt : 256;
    if (tid == 0) g_nzcnt[img] = cnt;
    for (int i = tid; i < cnt; i += blockDim.x)
        g_nzlist[img * 256 + i] = sList[i];
}

// ---------------------------------------------------------------------------
// Zero c1 (scatter target). float4 grid-stride.
// ---------------------------------------------------------------------------
__global__ void k_zero_c1() {
    int i = blockIdx.x * 256 + threadIdx.x;
    ((float4*)g_c1)[i] = make_float4(0.f, 0.f, 0.f, 0.f);
}

// ---------------------------------------------------------------------------
// Sparse conv1: one block per (b,ci) plane. Each warp takes one nonzero
// pixel; lanes = 32 output channels; RED.ADD to NHWC c1.
// ---------------------------------------------------------------------------
__global__ void k_scatter1(const float* __restrict__ w1) {
    int img = blockIdx.x;
    int b = img >> 2, ci = img & 3;
    __shared__ float sW[49 * 32];          // [ky*7+kx][oc]
    __shared__ unsigned short sList[256];
    __shared__ int sCnt;
    int tid = threadIdx.x;
    for (int i = tid; i < 49 * 32; i += 256) {
        int oc = i & 31; int r = i >> 5;
        int ky = r / 7, kx = r % 7;
        sW[i] = w1[((oc * 4 + ci) * 7 + ky) * 7 + kx];
    }
    if (tid == 0) sCnt = g_nzcnt[img];
    __syncthreads();
    int cnt = sCnt;
    for (int i = tid; i < cnt; i += 256) sList[i] = g_nzlist[img * 256 + i];
    __syncthreads();
    int warp = tid >> 5, lane = tid & 31;
    for (int e = warp; e < cnt; e += 8) {
        int ent = sList[e];
        int p = ent & 16383, code = ent >> 14;
        float v = (code == 0) ? 0.5f : ((code == 1) ? 1.0f : -1.0f);
        int iy = p >> 7, ix = p & 127;
        #pragma unroll
        for (int ky = 0; ky < 7; ky++) {
            int t = iy + 3 - ky;
            if (t < 0 || t >= 128 || (t & 1)) continue;
            int oy = t >> 1;
            #pragma unroll
            for (int kx = 0; kx < 7; kx++) {
                int u = ix + 3 - kx;
                if (u < 0 || u >= 128 || (u & 1)) continue;
                int ox = u >> 1;
                atomicAdd(&g_c1[((b * 64 + oy) * 64 + ox) * 32 + lane],
                          v * sW[(ky * 7 + kx) * 32 + lane]);
            }
        }
    }
}

// ---------------------------------------------------------------------------
// Pool1 3x3 s2 + bias + relu. NHWC -> NHWC. oc fastest (coalesced).
// ---------------------------------------------------------------------------
__global__ void k_pool1(const float* __restrict__ b1) {
    int idx = blockIdx.x * 256 + threadIdx.x;     // exactly 512*961*32
    int oc = idx & 31; int t = idx >> 5;
    int px = t % 31; int py = (t / 31) % 31; int b = t / 961;
    const float* ip = g_c1 + ((size_t)(b * 64 + 2 * py) * 64 + 2 * px) * 32 + oc;
    float m = -CUDART_INF_F;
    #pragma unroll
    for (int dy = 0; dy < 3; dy++)
        #pragma unroll
        for (int dx = 0; dx < 3; dx++)
            m = fmaxf(m, ip[(dy * 64 + dx) * 32]);
    float v = m + b1[oc];
    g_p1[idx] = v > 0.f ? v : 0.f;
}

// ---------------------------------------------------------------------------
// Conv2 5x5 s1 p2, 32->64 + relu. grid (512,4), block 256.
// Thread = 8 oc x 8 px. Tile 16x16 px. ci chunked by 4.
// ---------------------------------------------------------------------------
__global__ __launch_bounds__(256, 2) void k_conv2(const float* __restrict__ w2,
                                                  const float* __restrict__ b2) {
    __shared__ __align__(16) float sW[4 * 25 * 64];   // [ci][ky][kx][oc]
    __shared__ float sIn[4][20][21];
    int b = blockIdx.x, tile = blockIdx.y;
    int y0 = (tile >> 1) * 16, x0 = (tile & 1) * 16;
    int tid = threadIdx.x;
    int oc_g = tid >> 5, lane = tid & 31;
    int row = lane >> 1, colh = lane & 1;

    float acc[8][8];
    #pragma unroll
    for (int k = 0; k < 8; k++)
        #pragma unroll
        for (int j = 0; j < 8; j++) acc[k][j] = 0.f;

    for (int c0 = 0; c0 < 32; c0 += 4) {
        __syncthreads();
        for (int i = tid; i < 6400; i += 256) {
            int oc = i & 63; int r = i >> 6;
            int kx = r % 5; int q = r / 5; int ky = q % 5; int ci = q / 5;
            sW[i] = w2[((oc * 32 + c0 + ci) * 5 + ky) * 5 + kx];
        }
        for (int i = tid; i < 1600; i += 256) {
            int ci = i & 3; int t = i >> 2;
            int cc = t % 20; int rr = t / 20;
            int gy = y0 - 2 + rr, gx = x0 - 2 + cc;
            float v = 0.f;
            if (gy >= 0 && gy < 31 && gx >= 0 && gx < 31)
                v = g_p1[((size_t)(b * 31 + gy) * 31 + gx) * 32 + c0 + ci];
            sIn[ci][rr][cc] = v;
        }
        __syncthreads();
        for (int ci = 0; ci < 4; ci++)
            for (int ky = 0; ky < 5; ky++)
                #pragma unroll
                for (int kx = 0; kx < 5; kx++) {
                    const float* wp = &sW[((ci * 5 + ky) * 5 + kx) * 64 + oc_g * 8];
                    float4 wa = *(const float4*)wp;
                    float4 wb = *(const float4*)(wp + 4);
                    float in[8];
                    #pragma unroll
                    for (int j = 0; j < 8; j++)
                        in[j] = sIn[ci][row + ky][colh * 8 + kx + j];
                    #pragma unroll
                    for (int j = 0; j < 8; j++) {
                        acc[0][j] += wa.x * in[j];
                        acc[1][j] += wa.y * in[j];
                        acc[2][j] += wa.z * in[j];
                        acc[3][j] += wa.w * in[j];
                        acc[4][j] += wb.x * in[j];
                        acc[5][j] += wb.y * in[j];
                        acc[6][j] += wb.z * in[j];
                        acc[7][j] += wb.w * in[j];
                    }
                }
    }

    float bb[8];
    #pragma unroll
    for (int k = 0; k < 8; k++) bb[k] = b2[oc_g * 8 + k];
    int oy = y0 + row;
    #pragma unroll
    for (int j = 0; j < 8; j++) {
        int ox = x0 + colh * 8 + j;
        if (oy < 31 && ox < 31) {
            float* op = &g_c2[((size_t)(b * 31 + oy) * 31 + ox) * 64 + oc_g * 8];
            float4 o1, o2;
            float v;
            v = acc[0][j] + bb[0]; o1.x = v > 0.f ? v : 0.f;
            v = acc[1][j] + bb[1]; o1.y = v > 0.f ? v : 0.f;
            v = acc[2][j] + bb[2]; o1.z = v > 0.f ? v : 0.f;
            v = acc[3][j] + bb[3]; o1.w = v > 0.f ? v : 0.f;
            v = acc[4][j] + bb[4]; o2.x = v > 0.f ? v : 0.f;
            v = acc[5][j] + bb[5]; o2.y = v > 0.f ? v : 0.f;
            v = acc[6][j] + bb[6]; o2.z = v > 0.f ? v : 0.f;
            v = acc[7][j] + bb[7]; o2.w = v > 0.f ? v : 0.f;
            *(float4*)op = o1;
            *(float4*)(op + 4) = o2;
        }
    }
}

// ---------------------------------------------------------------------------
// Pool2 2x2 s2. NHWC. oc fastest.
// ---------------------------------------------------------------------------
__global__ void k_pool2() {
    int idx = blockIdx.x * 256 + threadIdx.x;     // exactly 512*225*64
    int oc = idx & 63; int t = idx >> 6;
    int px = t % 15; int py = (t / 15) % 15; int b = t / 225;
    const float* ip = g_c2 + ((size_t)(b * 31 + 2 * py) * 31 + 2 * px) * 64 + oc;
    float m = fmaxf(fmaxf(ip[0], ip[64]), fmaxf(ip[31 * 64], ip[32 * 64]));
    g_p2[idx] = m;
}

// ---------------------------------------------------------------------------
// Conv3 3x3 s1 p1, 64->128 + relu. grid (512,2), block 256.
// Thread = 8 oc x 8 px (flat over 225). ci chunked by 8.
// ---------------------------------------------------------------------------
__global__ __launch_bounds__(256, 2) void k_conv3(const float* __restrict__ w3,
                                                  const float* __restrict__ b3) {
    __shared__ __align__(16) float sW[8 * 9 * 64];   // [ci][ky*3+kx][oc]
    __shared__ float sIn[8 * 17 * 18];               // [ci][rr][cc], cc padded
    int b = blockIdx.x;
    int oc0 = blockIdx.y * 64;
    int tid = threadIdx.x;
    int oc_g = tid >> 5, lane = tid & 31;

    int base[8]; int pidx[8];
    #pragma unroll
    for (int j = 0; j < 8; j++) {
        int p = lane * 8 + j;
        pidx[j] = p;
        int r = p / 15, c = p % 15;
        base[j] = (p < 225) ? r * 18 + c : 0;
    }

    float acc[8][8];
    #pragma unroll
    for (int k = 0; k < 8; k++)
        #pragma unroll
        for (int j = 0; j < 8; j++) acc[k][j] = 0.f;

    for (int c0 = 0; c0 < 64; c0 += 8) {
        __syncthreads();
        for (int i = tid; i < 4608; i += 256) {
            int oc = i & 63; int r = i >> 6;
            int kx = r % 3; int ky = (r / 3) % 3; int ci = r / 9;
            sW[i] = w3[(((oc0 + oc) * 64 + c0 + ci) * 3 + ky) * 3 + kx];
        }
        for (int i = tid; i < 2312; i += 256) {
            int ci = i & 7; int t = i >> 3;
            int cc = t % 17; int rr = t / 17;
            int gy = rr - 1, gx = cc - 1;
            float v = 0.f;
            if (gy >= 0 && gy < 15 && gx >= 0 && gx < 15)
                v = g_p2[((size_t)(b * 15 + gy) * 15 + gx) * 64 + c0 + ci];
            sIn[ci * 306 + rr * 18 + cc] = v;
        }
        __syncthreads();
        for (int ci = 0; ci < 8; ci++)
            #pragma unroll
            for (int ky = 0; ky < 3; ky++)
                #pragma unroll
                for (int kx = 0; kx < 3; kx++) {
                    const float* wp = &sW[(ci * 9 + ky * 3 + kx) * 64 + oc_g * 8];
                    float4 wa = *(const float4*)wp;
                    float4 wb = *(const float4*)(wp + 4);
                    float in[8];
                    #pragma unroll
                    for (int j = 0; j < 8; j++)
                        in[j] = sIn[ci * 306 + base[j] + ky * 18 + kx];
                    #pragma unroll
                    for (int j = 0; j < 8; j++) {
                        acc[0][j] += wa.x * in[j];
                        acc[1][j] += wa.y * in[j];
                        acc[2][j] += wa.z * in[j];
                        acc[3][j] += wa.w * in[j];
                        acc[4][j] += wb.x * in[j];
                        acc[5][j] += wb.y * in[j];
                        acc[6][j] += wb.z * in[j];
                        acc[7][j] += wb.w * in[j];
                    }
                }
    }

    float bb[8];
    #pragma unroll
    for (int k = 0; k < 8; k++) bb[k] = b3[oc0 + oc_g * 8 + k];
    #pragma unroll
    for (int j = 0; j < 8; j++) {
        if (pidx[j] < 225) {
            float* op = &g_c3[((size_t)b * 225 + pidx[j]) * 128 + oc0 + oc_g * 8];
            float4 o1, o2;
            float v;
            v = acc[0][j] + bb[0]; o1.x = v > 0.f ? v : 0.f;
            v = acc[1][j] + bb[1]; o1.y = v > 0.f ? v : 0.f;
            v = acc[2][j] + bb[2]; o1.z = v > 0.f ? v : 0.f;
            v = acc[3][j] + bb[3]; o1.w = v > 0.f ? v : 0.f;
            v = acc[4][j] + bb[4]; o2.x = v > 0.f ? v : 0.f;
            v = acc[5][j] + bb[5]; o2.y = v > 0.f ? v : 0.f;
            v = acc[6][j] + bb[6]; o2.z = v > 0.f ? v : 0.f;
            v = acc[7][j] + bb[7]; o2.w = v > 0.f ? v : 0.f;
            *(float4*)op = o1;
            *(float4*)(op + 4) = o2;
        }
    }
}

// ---------------------------------------------------------------------------
// Pool3 (2x2 s2: 15->7) + mean. Thread per (b,oc), oc fastest (coalesced).
// ---------------------------------------------------------------------------
__global__ void k_avg() {
    int idx = blockIdx.x * 256 + threadIdx.x;   // 512*128
    int oc = idx & 127; int b = idx >> 7;
    const float* ip = g_c3 + (size_t)b * 225 * 128 + oc;
    float s = 0.f;
    #pragma unroll
    for (int py = 0; py < 7; py++)
        #pragma unroll
        for (int px = 0; px < 7; px++) {
            const float* w = ip + ((2 * py) * 15 + 2 * px) * 128;
            float m = fmaxf(fmaxf(w[0], w[128]), fmaxf(w[15 * 128], w[16 * 128]));
            s += m;
        }
    g_avg[idx] = s * (1.f / 49.f);
}

// ---------------------------------------------------------------------------
// FC: 128 -> 128 relu -> 5
// ---------------------------------------------------------------------------
__global__ void k_fc(const float* __restrict__ fw1, const float* __restrict__ fb1,
                     const float* __restrict__ fw2, const float* __restrict__ fb2,
                     float* __restrict__ out) {
    int b = blockIdx.x;
    int tid = threadIdx.x;
    __shared__ float sa[128], sh[128];
    sa[tid] = g_avg[b * 128 + tid];
    __syncthreads();
    float s = fb1[tid];
    const float* wr = fw1 + tid * 128;
    #pragma unroll 8
    for (int j = 0; j < 128; j++) s += wr[j] * sa[j];
    sh[tid] = s > 0.f ? s : 0.f;
    __syncthreads();
    if (tid < 5) {
        float o = fb2[tid];
        const float* wr2 = fw2 + tid * 128;
        #pragma unroll 8
        for (int j = 0; j < 128; j++) o += wr2[j] * sh[j];
        out[b * 5 + tid] = o;
    }
}

// ---------------------------------------------------------------------------
extern "C" void kernel_launch(void* const* d_in, const int* in_sizes, int n_in,
                              void* d_out, int out_size) {
    const int*   x   = (const int*)  d_in[0];
    const float* w1  = (const float*)d_in[1];
    const float* b1  = (const float*)d_in[2];
    const float* w2  = (const float*)d_in[3];
    const float* b2  = (const float*)d_in[4];
    const float* w3  = (const float*)d_in[5];
    const float* b3  = (const float*)d_in[6];
    const float* fw1 = (const float*)d_in[7];
    const float* fb1 = (const float*)d_in[8];
    const float* fw2 = (const float*)d_in[9];
    const float* fb2 = (const float*)d_in[10];
    float* out = (float*)d_out;

    k_raster_nz<<<NIMG, 256>>>(x);
    k_zero_c1<<<65536, 256>>>();                         // 67.1M floats / 4 / 256
    k_scatter1<<<NIMG, 256>>>(w1);
    k_pool1<<<(NB * 961 * 32) / 256, 256>>>(b1);         // 61504 blocks
    k_conv2<<<dim3(NB, 4), 256>>>(w2, b2);
    k_pool2<<<(NB * 225 * 64) / 256, 256>>>();           // 28800 blocks
    k_conv3<<<dim3(NB, 2), 256>>>(w3, b3);
    k_avg<<<(NB * 128) / 256, 256>>>();
    k_fc<<<NB, 128>>>(fw1, fb1, fw2, fb2, out);
}

// round 4
// speedup vs baseline: 3.9879x; 2.0315x over previous
#include <cuda_runtime.h>
#include <cuda_bf16.h>
#include <math_constants.h>

// ---------------------------------------------------------------------------
//   x [512,4,10,2] i32 -> nonzero list
//   conv1 7x7 s2 p3 4->32 : SPARSE scatter-add into c1 [512,64,64,32] NHWC
//   pool1 3x3 s2 (+bias+relu)        -> p1 [512,961,32]
//   conv2 5x5 s1 p2 32->64 (+relu)   -> c2 [512,961,64]   (tf32 mma)
//   pool2 2x2 s2                     -> p2 [512,225,64]
//   conv3 3x3 s1 p1 64->128 (+relu)  -> c3 [512,225,128]  (tf32 mma)
//   pool 2x2 s2 + mean               -> avg [512,128]
//   fc 128->128 relu -> 5            -> out [512,5]
//
// mma.m16n8k8.tf32 fragment maps (g=lane>>2, t=lane&3):
//   A: a0=(g,t) a1=(g+8,t) a2=(g,t+4) a3=(g+8,t+4)
//   B: b0=B[t][g] b1=B[t+4][g]
//   C: c0=(g,2t) c1=(g,2t+1) c2=(g+8,2t) c3=(g+8,2t+1)
// Channels are stored k-permuted within each 8-block: (0,4),(1,5),(2,6),(3,7)
// so thread t's k-pair (t, t+4) is contiguous -> uint2 loads.
// ---------------------------------------------------------------------------

#define NB 512
#define NIMG (NB * 4)

__device__ float g_c1 [NB * 64 * 64 * 32];
__device__ float g_p1 [NB * 961 * 32];
__device__ float g_c2 [NB * 961 * 64];
__device__ float g_p2 [NB * 225 * 64];
__device__ float g_c3 [NB * 225 * 128];
__device__ float g_avg[NB * 128];
__device__ int            g_nzcnt [NIMG];
__device__ unsigned short g_nzlist[NIMG * 256];

__device__ __forceinline__ unsigned f2tf(float f) {
    unsigned u; asm("cvt.rna.tf32.f32 %0, %1;" : "=r"(u) : "f"(f)); return u;
}

__device__ __forceinline__ void mma_tf32(float& c0, float& c1, float& c2, float& c3,
                                         unsigned a0, unsigned a1, unsigned a2, unsigned a3,
                                         unsigned b0, unsigned b1) {
    asm volatile("mma.sync.aligned.m16n8k8.row.col.f32.tf32.tf32.f32 "
                 "{%0,%1,%2,%3},{%4,%5,%6,%7},{%8,%9},{%0,%1,%2,%3};"
                 : "+f"(c0), "+f"(c1), "+f"(c2), "+f"(c3)
                 : "r"(a0), "r"(a1), "r"(a2), "r"(a3), "r"(b0), "r"(b1));
}

// ---------------------------------------------------------------------------
// Rasterize to nonzero list. Entry: p | code<<14; code 0=0.5, 1=1.0, 2=-1.0
// ---------------------------------------------------------------------------
__global__ void k_raster_nz(const int* __restrict__ x) {
    int img = blockIdx.x;
    __shared__ int ax[9], ay[9];
    __shared__ int sdX, sloX, shiX, sloY, shiY;
    __shared__ int sCnt;
    __shared__ unsigned short sList[256];
    int tid = threadIdx.x;
    if (tid < 9) {
        int vx = x[img * 20 + tid * 2 + 0];
        int vy = x[img * 20 + tid * 2 + 1];
        ax[tid] = ((vx + 64) % 127 + 127) % 127;
        ay[tid] = ((64 - vy) % 127 + 127) % 127;
    }
    if (tid == 9) {
        int vx = x[img * 20 + 18];
        int vy = x[img * 20 + 19];
        int dX = 64 + vx, dY = 64 - vy;
        sdX = dX;
        sloX = (dX >= 64) ? 64 : dX + 1;
        shiX = (dX >= 64) ? dX - 1 : 64;
        sloY = (dY >= 64) ? 64 : dY + 1;
        shiY = (dY >= 64) ? dY - 1 : 64;
    }
    if (tid == 10) sCnt = 0;
    __syncthreads();
    for (int p = tid; p < 16384; p += blockDim.x) {
        int y = p >> 7, xx = p & 127;
        float val = 0.f;
        if (y == 64 && xx >= sloX && xx <= shiX) val = -1.f;
        if (xx == sdX && y >= sloY && y <= shiY) val = -1.f;
        if (y >= 63 && y <= 65 && xx >= 63 && xx <= 65)
            val = (y == 64 && xx == 64) ? 1.f : 0.5f;
        #pragma unroll
        for (int k = 0; k < 9; k++) {
            int dy = y - ay[k], dx = xx - ax[k];
            if (dy >= -1 && dy <= 1 && dx >= -1 && dx <= 1)
                val = (dy == 0 && dx == 0) ? 1.f : 0.5f;
        }
        if (val != 0.f) {
            int pos = atomicAdd(&sCnt, 1);
            if (pos < 256) {
                int code = (val == 0.5f) ? 0 : ((val == 1.f) ? 1 : 2);
                sList[pos] = (unsigned short)(p | (code << 14));
            }
        }
    }
    __syncthreads();
    int cnt = sCnt < 256 ? sCnt : 256;
    if (tid == 0) g_nzcnt[img] = cnt;
    for (int i = tid; i < cnt; i += blockDim.x)
        g_nzlist[img * 256 + i] = sList[i];
}

__global__ void k_zero_c1() {
    int i = blockIdx.x * 256 + threadIdx.x;
    ((float4*)g_c1)[i] = make_float4(0.f, 0.f, 0.f, 0.f);
}

// ---------------------------------------------------------------------------
// Sparse conv1: block per (b,ci). Warp = one nonzero pixel, lanes = 32 oc.
// ---------------------------------------------------------------------------
__global__ void k_scatter1(const float* __restrict__ w1) {
    int img = blockIdx.x;
    int b = img >> 2, ci = img & 3;
    __shared__ float sW[49 * 32];
    __shared__ unsigned short sList[256];
    __shared__ int sCnt;
    int tid = threadIdx.x;
    for (int i = tid; i < 49 * 32; i += 256) {
        int oc = i & 31; int r = i >> 5;
        int ky = r / 7, kx = r % 7;
        sW[i] = w1[((oc * 4 + ci) * 7 + ky) * 7 + kx];
    }
    if (tid == 0) sCnt = g_nzcnt[img];
    __syncthreads();
    int cnt = sCnt;
    for (int i = tid; i < cnt; i += 256) sList[i] = g_nzlist[img * 256 + i];
    __syncthreads();
    int warp = tid >> 5, lane = tid & 31;
    for (int e = warp; e < cnt; e += 8) {
        int ent = sList[e];
        int p = ent & 16383, code = ent >> 14;
        float v = (code == 0) ? 0.5f : ((code == 1) ? 1.0f : -1.0f);
        int iy = p >> 7, ix = p & 127;
        #pragma unroll
        for (int ky = 0; ky < 7; ky++) {
            int t = iy + 3 - ky;
            if (t < 0 || t >= 128 || (t & 1)) continue;
            int oy = t >> 1;
            #pragma unroll
            for (int kx = 0; kx < 7; kx++) {
                int u = ix + 3 - kx;
                if (u < 0 || u >= 128 || (u & 1)) continue;
                int ox = u >> 1;
                atomicAdd(&g_c1[((b * 64 + oy) * 64 + ox) * 32 + lane],
                          v * sW[(ky * 7 + kx) * 32 + lane]);
            }
        }
    }
}

// ---------------------------------------------------------------------------
// Pool1 3x3 s2 + bias + relu
// ---------------------------------------------------------------------------
__global__ void k_pool1(const float* __restrict__ b1) {
    int idx = blockIdx.x * 256 + threadIdx.x;
    int oc = idx & 31; int t = idx >> 5;
    int px = t % 31; int py = (t / 31) % 31; int b = t / 961;
    const float* ip = g_c1 + ((size_t)(b * 64 + 2 * py) * 64 + 2 * px) * 32 + oc;
    float m = -CUDART_INF_F;
    #pragma unroll
    for (int dy = 0; dy < 3; dy++)
        #pragma unroll
        for (int dx = 0; dx < 3; dx++)
            m = fmaxf(m, ip[(dy * 64 + dx) * 32]);
    float v = m + b1[oc];
    g_p1[idx] = v > 0.f ? v : 0.f;
}

// ---------------------------------------------------------------------------
// Conv2 via tf32 mma. grid (512, 2), block 256 (8 warps).
// Warp: 64 px (4 m16 tiles) x 64 oc (8 n8 tiles). K = 32 ci x 25 taps.
// ---------------------------------------------------------------------------
#define C2_SIN   (961 * 36)
#define C2_SMEM  ((C2_SIN + 2 * 2048) * 4)

extern __shared__ unsigned smem_u[];

__global__ __launch_bounds__(256, 1) void k_conv2_mma(const float* __restrict__ w2,
                                                      const float* __restrict__ b2) {
    unsigned* sIn = smem_u;
    unsigned* wfA = smem_u + C2_SIN;
    unsigned* wfB = wfA + 2048;
    int b = blockIdx.x;
    int tid = threadIdx.x;
    int warp = tid >> 5, lane = tid & 31;
    int g = lane >> 2, t = lane & 3;

    const float* src = g_p1 + (size_t)b * 30752;
    for (int i = tid; i < 30752; i += 256) {
        int p = i >> 5, c = i & 31;
        int cb = c & 7;
        int cp = (c & ~7) | (2 * (cb & 3) + (cb >> 2));   // k-permute (0,4),(1,5),(2,6),(3,7)
        sIn[p * 36 + cp] = f2tf(src[i]);
    }
    for (int i = tid; i < 2048; i += 256) {
        int h = i & 1, ln = (i >> 1) & 31, j = (i >> 6) & 7, ks = i >> 9;
        int k = ks * 8 + (ln & 3) + 4 * h;                // b0: k=t, b1: k=t+4
        int n = j * 8 + (ln >> 2);
        wfA[i] = f2tf(w2[n * 800 + k * 25]);
    }
    __syncthreads();

    int p0 = blockIdx.y * 512 + warp * 64;
    int prow[8], ppy[8], ppx[8];
    #pragma unroll
    for (int mt = 0; mt < 4; mt++)
        #pragma unroll
        for (int h = 0; h < 2; h++) {
            int i = mt * 2 + h;
            int p = p0 + mt * 16 + g + h * 8;
            prow[i] = p; ppy[i] = p / 31; ppx[i] = p - ppy[i] * 31;
        }

    float acc[4][8][4];
    #pragma unroll
    for (int mt = 0; mt < 4; mt++)
        #pragma unroll
        for (int j = 0; j < 8; j++)
            #pragma unroll
            for (int q = 0; q < 4; q++) acc[mt][j][q] = 0.f;

    #pragma unroll 1
    for (int tap = 0; tap < 25; tap++) {
        unsigned* cur = (tap & 1) ? wfB : wfA;
        unsigned* nxt = (tap & 1) ? wfA : wfB;
        if (tap + 1 < 25) {
            for (int i = tid; i < 2048; i += 256) {
                int h = i & 1, ln = (i >> 1) & 31, j = (i >> 6) & 7, ks = i >> 9;
                int k = ks * 8 + (ln & 3) + 4 * h;
                int n = j * 8 + (ln >> 2);
                nxt[i] = f2tf(w2[n * 800 + k * 25 + tap + 1]);
            }
        }
        int ky = tap / 5, kx = tap - ky * 5;
        int shift = (ky - 2) * 31 + (kx - 2);
        bool val[8]; int aoff[8];
        #pragma unroll
        for (int i = 0; i < 8; i++) {
            val[i] = (prow[i] < 961) && ((unsigned)(ppy[i] + ky - 2) < 31u)
                                     && ((unsigned)(ppx[i] + kx - 2) < 31u);
            aoff[i] = (prow[i] + shift) * 36 + 2 * t;
        }
        #pragma unroll
        for (int ks = 0; ks < 4; ks++) {
            int k0 = ks * 8;
            uint2 B[8];
            #pragma unroll
            for (int j = 0; j < 8; j++)
                B[j] = *(const uint2*)&cur[((ks * 8 + j) * 32 + lane) * 2];
            #pragma unroll
            for (int mt = 0; mt < 4; mt++) {
                uint2 A0 = make_uint2(0u, 0u), A1 = make_uint2(0u, 0u);
                if (val[2 * mt])     A0 = *(const uint2*)&sIn[aoff[2 * mt] + k0];
                if (val[2 * mt + 1]) A1 = *(const uint2*)&sIn[aoff[2 * mt + 1] + k0];
                #pragma unroll
                for (int j = 0; j < 8; j++)
                    mma_tf32(acc[mt][j][0], acc[mt][j][1], acc[mt][j][2], acc[mt][j][3],
                             A0.x, A1.x, A0.y, A1.y, B[j].x, B[j].y);
            }
        }
        __syncthreads();
    }

    #pragma unroll
    for (int j = 0; j < 8; j++) {
        int oc = j * 8 + 2 * t;
        float2 bb = *(const float2*)&b2[oc];
        #pragma unroll
        for (int mt = 0; mt < 4; mt++) {
            int plo = prow[mt * 2], phi = prow[mt * 2 + 1];
            if (plo < 961) {
                float2 o;
                o.x = fmaxf(acc[mt][j][0] + bb.x, 0.f);
                o.y = fmaxf(acc[mt][j][1] + bb.y, 0.f);
                *(float2*)&g_c2[((size_t)b * 961 + plo) * 64 + oc] = o;
            }
            if (phi < 961) {
                float2 o;
                o.x = fmaxf(acc[mt][j][2] + bb.x, 0.f);
                o.y = fmaxf(acc[mt][j][3] + bb.y, 0.f);
                *(float2*)&g_c2[((size_t)b * 961 + phi) * 64 + oc] = o;
            }
        }
    }
}

// ---------------------------------------------------------------------------
// Pool2 2x2 s2
// ---------------------------------------------------------------------------
__global__ void k_pool2() {
    int idx = blockIdx.x * 256 + threadIdx.x;
    int oc = idx & 63; int t = idx >> 6;
    int px = t % 15; int py = (t / 15) % 15; int b = t / 225;
    const float* ip = g_c2 + ((size_t)(b * 31 + 2 * py) * 31 + 2 * px) * 64 + oc;
    float m = fmaxf(fmaxf(ip[0], ip[64]), fmaxf(ip[31 * 64], ip[32 * 64]));
    g_p2[idx] = m;
}

// ---------------------------------------------------------------------------
// Conv3 via tf32 mma. grid (512), block 256.
// Warp (w): px quarter = (w&3)*64, oc half = (w>>2)*64. K = 64 ci x 9 taps.
// ---------------------------------------------------------------------------
#define C3_SIN   (225 * 68)
#define C3_SMEM  ((C3_SIN + 2 * 8192) * 4)

__global__ __launch_bounds__(256, 1) void k_conv3_mma(const float* __restrict__ w3,
                                                      const float* __restrict__ b3) {
    unsigned* sIn = smem_u;
    unsigned* wfA = smem_u + C3_SIN;
    unsigned* wfB = wfA + 8192;
    int b = blockIdx.x;
    int tid = threadIdx.x;
    int warp = tid >> 5, lane = tid & 31;
    int g = lane >> 2, t = lane & 3;

    const float* src = g_p2 + (size_t)b * 14400;
    for (int i = tid; i < 14400; i += 256) {
        int p = i >> 6, c = i & 63;
        int cb = c & 7;
        int cp = (c & ~7) | (2 * (cb & 3) + (cb >> 2));
        sIn[p * 68 + cp] = f2tf(src[i]);
    }
    for (int i = tid; i < 8192; i += 256) {
        int h = i & 1, ln = (i >> 1) & 31, j = (i >> 6) & 7, ks = (i >> 9) & 7, half = i >> 12;
        int k = ks * 8 + (ln & 3) + 4 * h;
        int oc = half * 64 + j * 8 + (ln >> 2);
        wfA[i] = f2tf(w3[oc * 576 + k * 9]);
    }
    __syncthreads();

    int p0 = (warp & 3) * 64;
    int ochalf = warp >> 2;
    int prow[8], ppy[8], ppx[8];
    #pragma unroll
    for (int mt = 0; mt < 4; mt++)
        #pragma unroll
        for (int h = 0; h < 2; h++) {
            int i = mt * 2 + h;
            int p = p0 + mt * 16 + g + h * 8;
            prow[i] = p; ppy[i] = p / 15; ppx[i] = p - ppy[i] * 15;
        }

    float acc[4][8][4];
    #pragma unroll
    for (int mt = 0; mt < 4; mt++)
        #pragma unroll
        for (int j = 0; j < 8; j++)
            #pragma unroll
            for (int q = 0; q < 4; q++) acc[mt][j][q] = 0.f;

    #pragma unroll 1
    for (int tap = 0; tap < 9; tap++) {
        unsigned* cur = (tap & 1) ? wfB : wfA;
        unsigned* nxt = (tap & 1) ? wfA : wfB;
        if (tap + 1 < 9) {
            for (int i = tid; i < 8192; i += 256) {
                int h = i & 1, ln = (i >> 1) & 31, j = (i >> 6) & 7, ks = (i >> 9) & 7, half = i >> 12;
                int k = ks * 8 + (ln & 3) + 4 * h;
                int oc = half * 64 + j * 8 + (ln >> 2);
                nxt[i] = f2tf(w3[oc * 576 + k * 9 + tap + 1]);
            }
        }
        int ky = tap / 3, kx = tap - ky * 3;
        int shift = (ky - 1) * 15 + (kx - 1);
        bool val[8]; int aoff[8];
        #pragma unroll
        for (int i = 0; i < 8; i++) {
            val[i] = (prow[i] < 225) && ((unsigned)(ppy[i] + ky - 1) < 15u)
                                     && ((unsigned)(ppx[i] + kx - 1) < 15u);
            aoff[i] = (prow[i] + shift) * 68 + 2 * t;
        }
        #pragma unroll
        for (int ks = 0; ks < 8; ks++) {
            int k0 = ks * 8;
            uint2 B[8];
            #pragma unroll
            for (int j = 0; j < 8; j++)
                B[j] = *(const uint2*)&cur[ochalf * 4096 + ((ks * 8 + j) * 32 + lane) * 2];
            #pragma unroll
            for (int mt = 0; mt < 4; mt++) {
                uint2 A0 = make_uint2(0u, 0u), A1 = make_uint2(0u, 0u);
                if (val[2 * mt])     A0 = *(const uint2*)&sIn[aoff[2 * mt] + k0];
                if (val[2 * mt + 1]) A1 = *(const uint2*)&sIn[aoff[2 * mt + 1] + k0];
                #pragma unroll
                for (int j = 0; j < 8; j++)
                    mma_tf32(acc[mt][j][0], acc[mt][j][1], acc[mt][j][2], acc[mt][j][3],
                             A0.x, A1.x, A0.y, A1.y, B[j].x, B[j].y);
            }
        }
        __syncthreads();
    }

    #pragma unroll
    for (int j = 0; j < 8; j++) {
        int oc = ochalf * 64 + j * 8 + 2 * t;
        float2 bb = *(const float2*)&b3[oc];
        #pragma unroll
        for (int mt = 0; mt < 4; mt++) {
            int plo = prow[mt * 2], phi = prow[mt * 2 + 1];
            if (plo < 225) {
                float2 o;
                o.x = fmaxf(acc[mt][j][0] + bb.x, 0.f);
                o.y = fmaxf(acc[mt][j][1] + bb.y, 0.f);
                *(float2*)&g_c3[((size_t)b * 225 + plo) * 128 + oc] = o;
            }
            if (phi < 225) {
                float2 o;
                o.x = fmaxf(acc[mt][j][2] + bb.x, 0.f);
                o.y = fmaxf(acc[mt][j][3] + bb.y, 0.f);
                *(float2*)&g_c3[((size_t)b * 225 + phi) * 128 + oc] = o;
            }
        }
    }
}

// ---------------------------------------------------------------------------
// Pool3 + mean
// ---------------------------------------------------------------------------
__global__ void k_avg() {
    int idx = blockIdx.x * 256 + threadIdx.x;
    int oc = idx & 127; int b = idx >> 7;
    const float* ip = g_c3 + (size_t)b * 225 * 128 + oc;
    float s = 0.f;
    #pragma unroll
    for (int py = 0; py < 7; py++)
        #pragma unroll
        for (int px = 0; px < 7; px++) {
            const float* w = ip + ((2 * py) * 15 + 2 * px) * 128;
            float m = fmaxf(fmaxf(w[0], w[128]), fmaxf(w[15 * 128], w[16 * 128]));
            s += m;
        }
    g_avg[idx] = s * (1.f / 49.f);
}

__global__ void k_fc(const float* __restrict__ fw1, const float* __restrict__ fb1,
                     const float* __restrict__ fw2, const float* __restrict__ fb2,
                     float* __restrict__ out) {
    int b = blockIdx.x;
    int tid = threadIdx.x;
    __shared__ float sa[128], sh[128];
    sa[tid] = g_avg[b * 128 + tid];
    __syncthreads();
    float s = fb1[tid];
    const float* wr = fw1 + tid * 128;
    #pragma unroll 8
    for (int j = 0; j < 128; j++) s += wr[j] * sa[j];
    sh[tid] = s > 0.f ? s : 0.f;
    __syncthreads();
    if (tid < 5) {
        float o = fb2[tid];
        const float* wr2 = fw2 + tid * 128;
        #pragma unroll 8
        for (int j = 0; j < 128; j++) o += wr2[j] * sh[j];
        out[b * 5 + tid] = o;
    }
}

// ---------------------------------------------------------------------------
extern "C" void kernel_launch(void* const* d_in, const int* in_sizes, int n_in,
                              void* d_out, int out_size) {
    const int*   x   = (const int*)  d_in[0];
    const float* w1  = (const float*)d_in[1];
    const float* b1  = (const float*)d_in[2];
    const float* w2  = (const float*)d_in[3];
    const float* b2  = (const float*)d_in[4];
    const float* w3  = (const float*)d_in[5];
    const float* b3  = (const float*)d_in[6];
    const float* fw1 = (const float*)d_in[7];
    const float* fb1 = (const float*)d_in[8];
    const float* fw2 = (const float*)d_in[9];
    const float* fb2 = (const float*)d_in[10];
    float* out = (float*)d_out;

    cudaFuncSetAttribute(k_conv2_mma, cudaFuncAttributeMaxDynamicSharedMemorySize, C2_SMEM);
    cudaFuncSetAttribute(k_conv3_mma, cudaFuncAttributeMaxDynamicSharedMemorySize, C3_SMEM);

    k_raster_nz<<<NIMG, 256>>>(x);
    k_zero_c1<<<65536, 256>>>();
    k_scatter1<<<NIMG, 256>>>(w1);
    k_pool1<<<(NB * 961 * 32) / 256, 256>>>(b1);
    k_conv2_mma<<<dim3(NB, 2), 256, C2_SMEM>>>(w2, b2);
    k_pool2<<<(NB * 225 * 64) / 256, 256>>>();
    k_conv3_mma<<<NB, 256, C3_SMEM>>>(w3, b3);
    k_avg<<<(NB * 128) / 256, 256>>>();
    k_fc<<<NB, 128>>>(fw1, fb1, fw2, fb2, out);
}

// round 5
// speedup vs baseline: 4.8436x; 1.2146x over previous
#include <cuda_runtime.h>
#include <cuda_bf16.h>
#include <cuda_fp16.h>
#include <math_constants.h>

// ---------------------------------------------------------------------------
//   x [512,4,10,2] i32 -> nonzero list
//   conv1 7x7 s2 p3 4->32 : SPARSE scatter-add into c1 [512,64,64,32] NHWC
//   pool1 3x3 s2 (+bias+relu)        -> p1 [512,961,32]
//   conv2 5x5 s1 p2 32->64 (+relu)   -> c2 [512,961,64]   (fp16 mma, f32 accum)
//   pool2 2x2 s2                     -> p2 [512,225,64]
//   conv3 3x3 s1 p1 64->128 (+relu)  -> c3 [512,225,128]  (fp16 mma, f32 accum)
//   pool 2x2 s2 + mean               -> avg [512,128]
//   fc 128->128 relu -> 5            -> out [512,5]
//
// mma.m16n8k16.f16 fragment maps (g=lane>>2, t=lane&3), f16x2 regs:
//   A: a0=(g, 2t:2t+1) a1=(g+8, 2t:2t+1) a2=(g, 2t+8:2t+9) a3=(g+8, 2t+8:2t+9)
//   B: b0=B[2t:2t+1][g] b1=B[2t+8:2t+9][g]
//   C: c0=(g,2t) c1=(g,2t+1) c2=(g+8,2t) c3=(g+8,2t+1)
// Channel pairs (uint = f16x2 of ch 2q,2q+1) are stored permuted within each
// 8-pair (16-channel) chunk: (0,4),(1,5),(2,6),(3,7), so thread t's uint2 at
// offset 2t yields pairs (t, t+4) = k (2t,2t+1) and (2t+8,2t+9).
// ---------------------------------------------------------------------------

#define NB 512
#define NIMG (NB * 4)

__device__ float g_c1 [NB * 64 * 64 * 32];
__device__ float g_p1 [NB * 961 * 32];
__device__ float g_c2 [NB * 961 * 64];
__device__ float g_p2 [NB * 225 * 64];
__device__ float g_c3 [NB * 225 * 128];
__device__ float g_avg[NB * 128];
__device__ int            g_nzcnt [NIMG];
__device__ unsigned short g_nzlist[NIMG * 256];

__device__ __forceinline__ unsigned packh2(float a, float b) {
    __half2 h = __floats2half2_rn(a, b);
    return *(unsigned*)&h;
}

__device__ __forceinline__ void mma_f16(float& c0, float& c1, float& c2, float& c3,
                                        unsigned a0, unsigned a1, unsigned a2, unsigned a3,
                                        unsigned b0, unsigned b1) {
    asm volatile("mma.sync.aligned.m16n8k16.row.col.f32.f16.f16.f32 "
                 "{%0,%1,%2,%3},{%4,%5,%6,%7},{%8,%9},{%0,%1,%2,%3};"
                 : "+f"(c0), "+f"(c1), "+f"(c2), "+f"(c3)
                 : "r"(a0), "r"(a1), "r"(a2), "r"(a3), "r"(b0), "r"(b1));
}

// ---------------------------------------------------------------------------
// Rasterize to nonzero list. Entry: p | code<<14; code 0=0.5, 1=1.0, 2=-1.0
// ---------------------------------------------------------------------------
__global__ void k_raster_nz(const int* __restrict__ x) {
    int img = blockIdx.x;
    __shared__ int ax[9], ay[9];
    __shared__ int sdX, sloX, shiX, sloY, shiY;
    __shared__ int sCnt;
    __shared__ unsigned short sList[256];
    int tid = threadIdx.x;
    if (tid < 9) {
        int vx = x[img * 20 + tid * 2 + 0];
        int vy = x[img * 20 + tid * 2 + 1];
        ax[tid] = ((vx + 64) % 127 + 127) % 127;
        ay[tid] = ((64 - vy) % 127 + 127) % 127;
    }
    if (tid == 9) {
        int vx = x[img * 20 + 18];
        int vy = x[img * 20 + 19];
        int dX = 64 + vx, dY = 64 - vy;
        sdX = dX;
        sloX = (dX >= 64) ? 64 : dX + 1;
        shiX = (dX >= 64) ? dX - 1 : 64;
        sloY = (dY >= 64) ? 64 : dY + 1;
        shiY = (dY >= 64) ? dY - 1 : 64;
    }
    if (tid == 10) sCnt = 0;
    __syncthreads();
    for (int p = tid; p < 16384; p += blockDim.x) {
        int y = p >> 7, xx = p & 127;
        float val = 0.f;
        if (y == 64 && xx >= sloX && xx <= shiX) val = -1.f;
        if (xx == sdX && y >= sloY && y <= shiY) val = -1.f;
        if (y >= 63 && y <= 65 && xx >= 63 && xx <= 65)
            val = (y == 64 && xx == 64) ? 1.f : 0.5f;
        #pragma unroll
        for (int k = 0; k < 9; k++) {
            int dy = y - ay[k], dx = xx - ax[k];
            if (dy >= -1 && dy <= 1 && dx >= -1 && dx <= 1)
                val = (dy == 0 && dx == 0) ? 1.f : 0.5f;
        }
        if (val != 0.f) {
            int pos = atomicAdd(&sCnt, 1);
            if (pos < 256) {
                int code = (val == 0.5f) ? 0 : ((val == 1.f) ? 1 : 2);
                sList[pos] = (unsigned short)(p | (code << 14));
            }
        }
    }
    __syncthreads();
    int cnt = sCnt < 256 ? sCnt : 256;
    if (tid == 0) g_nzcnt[img] = cnt;
    for (int i = tid; i < cnt; i += blockDim.x)
        g_nzlist[img * 256 + i] = sList[i];
}

__global__ void k_zero_c1() {
    int i = blockIdx.x * 256 + threadIdx.x;
    ((float4*)g_c1)[i] = make_float4(0.f, 0.f, 0.f, 0.f);
}

// ---------------------------------------------------------------------------
// Sparse conv1: block per (b,ci). Warp = one nonzero pixel, lanes = 32 oc.
// ---------------------------------------------------------------------------
__global__ void k_scatter1(const float* __restrict__ w1) {
    int img = blockIdx.x;
    int b = img >> 2, ci = img & 3;
    __shared__ float sW[49 * 32];
    __shared__ unsigned short sList[256];
    __shared__ int sCnt;
    int tid = threadIdx.x;
    for (int i = tid; i < 49 * 32; i += 256) {
        int oc = i & 31; int r = i >> 5;
        int ky = r / 7, kx = r % 7;
        sW[i] = w1[((oc * 4 + ci) * 7 + ky) * 7 + kx];
    }
    if (tid == 0) sCnt = g_nzcnt[img];
    __syncthreads();
    int cnt = sCnt;
    for (int i = tid; i < cnt; i += 256) sList[i] = g_nzlist[img * 256 + i];
    __syncthreads();
    int warp = tid >> 5, lane = tid & 31;
    for (int e = warp; e < cnt; e += 8) {
        int ent = sList[e];
        int p = ent & 16383, code = ent >> 14;
        float v = (code == 0) ? 0.5f : ((code == 1) ? 1.0f : -1.0f);
        int iy = p >> 7, ix = p & 127;
        #pragma unroll
        for (int ky = 0; ky < 7; ky++) {
            int t = iy + 3 - ky;
            if (t < 0 || t >= 128 || (t & 1)) continue;
            int oy = t >> 1;
            #pragma unroll
            for (int kx = 0; kx < 7; kx++) {
                int u = ix + 3 - kx;
                if (u < 0 || u >= 128 || (u & 1)) continue;
                int ox = u >> 1;
                atomicAdd(&g_c1[((b * 64 + oy) * 64 + ox) * 32 + lane],
                          v * sW[(ky * 7 + kx) * 32 + lane]);
            }
        }
    }
}

// ---------------------------------------------------------------------------
// Pool1 3x3 s2 + bias + relu
// ---------------------------------------------------------------------------
__global__ void k_pool1(const float* __restrict__ b1) {
    int idx = blockIdx.x * 256 + threadIdx.x;
    int oc = idx & 31; int t = idx >> 5;
    int px = t % 31; int py = (t / 31) % 31; int b = t / 961;
    const float* ip = g_c1 + ((size_t)(b * 64 + 2 * py) * 64 + 2 * px) * 32 + oc;
    float m = -CUDART_INF_F;
    #pragma unroll
    for (int dy = 0; dy < 3; dy++)
        #pragma unroll
        for (int dx = 0; dx < 3; dx++)
            m = fmaxf(m, ip[(dy * 64 + dx) * 32]);
    float v = m + b1[oc];
    g_p1[idx] = v > 0.f ? v : 0.f;
}

// ---------------------------------------------------------------------------
// Conv2 via fp16 mma. grid (512, 2), block 256 (8 warps).
// Warp: 64 px (4 m16 tiles) x 64 oc (8 n8 tiles). K = 32 ci x 25 taps (2 ks).
// sIn: f16x2 pairs, stride 18 uints/px. wf: 1024 uints/tap, double-buffered.
// ---------------------------------------------------------------------------
#define C2_SIN   (961 * 18)
#define C2_WF    1024
#define C2_SMEM  ((C2_SIN + 2 * C2_WF) * 4)

extern __shared__ unsigned smem_u[];

__global__ __launch_bounds__(256, 1) void k_conv2_mma(const float* __restrict__ w2,
                                                      const float* __restrict__ b2) {
    unsigned* sIn = smem_u;
    unsigned* wfA = smem_u + C2_SIN;
    unsigned* wfB = wfA + C2_WF;
    int b = blockIdx.x;
    int tid = threadIdx.x;
    int warp = tid >> 5, lane = tid & 31;
    int g = lane >> 2, t = lane & 3;

    const float* src = g_p1 + (size_t)b * 30752;
    for (int i = tid; i < 961 * 16; i += 256) {
        int p = i >> 4, u = i & 15;
        int chunk = u >> 3, q = u & 7;
        int pos = 2 * (q & 3) + (q >> 2);
        float2 v = *(const float2*)&src[p * 32 + chunk * 16 + 2 * q];
        sIn[p * 18 + chunk * 8 + pos] = packh2(v.x, v.y);
    }
    for (int i = tid; i < C2_WF; i += 256) {
        int h = i & 1, ln = (i >> 1) & 31, j = (i >> 6) & 7, ks = i >> 9;
        int tt = ln & 3, gg = ln >> 2;
        int k = ks * 16 + 2 * tt + 8 * h;
        int n = j * 8 + gg;
        wfA[i] = packh2(w2[n * 800 + k * 25], w2[n * 800 + (k + 1) * 25]);
    }
    __syncthreads();

    int p0 = blockIdx.y * 512 + warp * 64;
    int prow[8], ppy[8], ppx[8];
    #pragma unroll
    for (int mt = 0; mt < 4; mt++)
        #pragma unroll
        for (int h = 0; h < 2; h++) {
            int i = mt * 2 + h;
            int p = p0 + mt * 16 + g + h * 8;
            prow[i] = p; ppy[i] = p / 31; ppx[i] = p - ppy[i] * 31;
        }

    float acc[4][8][4];
    #pragma unroll
    for (int mt = 0; mt < 4; mt++)
        #pragma unroll
        for (int j = 0; j < 8; j++)
            #pragma unroll
            for (int q = 0; q < 4; q++) acc[mt][j][q] = 0.f;

    #pragma unroll 1
    for (int tap = 0; tap < 25; tap++) {
        unsigned* cur = (tap & 1) ? wfB : wfA;
        unsigned* nxt = (tap & 1) ? wfA : wfB;
        if (tap + 1 < 25) {
            for (int i = tid; i < C2_WF; i += 256) {
                int h = i & 1, ln = (i >> 1) & 31, j = (i >> 6) & 7, ks = i >> 9;
                int tt = ln & 3, gg = ln >> 2;
                int k = ks * 16 + 2 * tt + 8 * h;
                int n = j * 8 + gg;
                nxt[i] = packh2(w2[n * 800 + k * 25 + tap + 1],
                                w2[n * 800 + (k + 1) * 25 + tap + 1]);
            }
        }
        int ky = tap / 5, kx = tap - ky * 5;
        int shift = (ky - 2) * 31 + (kx - 2);
        bool val[8]; int aoff[8];
        #pragma unroll
        for (int i = 0; i < 8; i++) {
            val[i] = (prow[i] < 961) && ((unsigned)(ppy[i] + ky - 2) < 31u)
                                     && ((unsigned)(ppx[i] + kx - 2) < 31u);
            aoff[i] = (prow[i] + shift) * 18 + 2 * t;
        }
        #pragma unroll
        for (int ks = 0; ks < 2; ks++) {
            int k0 = ks * 8;
            uint2 B[8];
            #pragma unroll
            for (int j = 0; j < 8; j++)
                B[j] = *(const uint2*)&cur[((ks * 8 + j) * 32 + lane) * 2];
            #pragma unroll
            for (int mt = 0; mt < 4; mt++) {
                uint2 A0 = make_uint2(0u, 0u), A1 = make_uint2(0u, 0u);
                if (val[2 * mt])     A0 = *(const uint2*)&sIn[aoff[2 * mt] + k0];
                if (val[2 * mt + 1]) A1 = *(const uint2*)&sIn[aoff[2 * mt + 1] + k0];
                #pragma unroll
                for (int j = 0; j < 8; j++)
                    mma_f16(acc[mt][j][0], acc[mt][j][1], acc[mt][j][2], acc[mt][j][3],
                            A0.x, A1.x, A0.y, A1.y, B[j].x, B[j].y);
            }
        }
        __syncthreads();
    }

    #pragma unroll
    for (int j = 0; j < 8; j++) {
        int oc = j * 8 + 2 * t;
        float2 bb = *(const float2*)&b2[oc];
        #pragma unroll
        for (int mt = 0; mt < 4; mt++) {
            int plo = prow[mt * 2], phi = prow[mt * 2 + 1];
            if (plo < 961) {
                float2 o;
                o.x = fmaxf(acc[mt][j][0] + bb.x, 0.f);
                o.y = fmaxf(acc[mt][j][1] + bb.y, 0.f);
                *(float2*)&g_c2[((size_t)b * 961 + plo) * 64 + oc] = o;
            }
            if (phi < 961) {
                float2 o;
                o.x = fmaxf(acc[mt][j][2] + bb.x, 0.f);
                o.y = fmaxf(acc[mt][j][3] + bb.y, 0.f);
                *(float2*)&g_c2[((size_t)b * 961 + phi) * 64 + oc] = o;
            }
        }
    }
}

// ---------------------------------------------------------------------------
// Pool2 2x2 s2
// ---------------------------------------------------------------------------
__global__ void k_pool2() {
    int idx = blockIdx.x * 256 + threadIdx.x;
    int oc = idx & 63; int t = idx >> 6;
    int px = t % 15; int py = (t / 15) % 15; int b = t / 225;
    const float* ip = g_c2 + ((size_t)(b * 31 + 2 * py) * 31 + 2 * px) * 64 + oc;
    float m = fmaxf(fmaxf(ip[0], ip[64]), fmaxf(ip[31 * 64], ip[32 * 64]));
    g_p2[idx] = m;
}

// ---------------------------------------------------------------------------
// Conv3 via fp16 mma. grid (512), block 256.
// Warp (w): px quarter = (w&3)*64, oc half = (w>>2)*64. K = 64 ci x 9 taps (4 ks).
// sIn: stride 34 uints/px. wf: 4096 uints/tap (2 halves), double-buffered.
// ---------------------------------------------------------------------------
#define C3_SIN   (225 * 34)
#define C3_WF    4096
#define C3_SMEM  ((C3_SIN + 2 * C3_WF) * 4)

__global__ __launch_bounds__(256, 1) void k_conv3_mma(const float* __restrict__ w3,
                                                      const float* __restrict__ b3) {
    unsigned* sIn = smem_u;
    unsigned* wfA = smem_u + C3_SIN;
    unsigned* wfB = wfA + C3_WF;
    int b = blockIdx.x;
    int tid = threadIdx.x;
    int warp = tid >> 5, lane = tid & 31;
    int g = lane >> 2, t = lane & 3;

    const float* src = g_p2 + (size_t)b * 14400;
    for (int i = tid; i < 225 * 32; i += 256) {
        int p = i >> 5, u = i & 31;
        int chunk = u >> 3, q = u & 7;
        int pos = 2 * (q & 3) + (q >> 2);
        float2 v = *(const float2*)&src[p * 64 + chunk * 16 + 2 * q];
        sIn[p * 34 + chunk * 8 + pos] = packh2(v.x, v.y);
    }
    for (int i = tid; i < C3_WF; i += 256) {
        int h = i & 1, ln = (i >> 1) & 31, j = (i >> 6) & 7, ks = (i >> 9) & 3, half = i >> 11;
        int tt = ln & 3, gg = ln >> 2;
        int k = ks * 16 + 2 * tt + 8 * h;
        int oc = half * 64 + j * 8 + gg;
        wfA[i] = packh2(w3[oc * 576 + k * 9], w3[oc * 576 + (k + 1) * 9]);
    }
    __syncthreads();

    int p0 = (warp & 3) * 64;
    int ochalf = warp >> 2;
    int prow[8], ppy[8], ppx[8];
    #pragma unroll
    for (int mt = 0; mt < 4; mt++)
        #pragma unroll
        for (int h = 0; h < 2; h++) {
            int i = mt * 2 + h;
            int p = p0 + mt * 16 + g + h * 8;
            prow[i] = p; ppy[i] = p / 15; ppx[i] = p - ppy[i] * 15;
        }

    float acc[4][8][4];
    #pragma unroll
    for (int mt = 0; mt < 4; mt++)
        #pragma unroll
        for (int j = 0; j < 8; j++)
            #pragma unroll
            for (int q = 0; q < 4; q++) acc[mt][j][q] = 0.f;

    #pragma unroll 1
    for (int tap = 0; tap < 9; tap++) {
        unsigned* cur = (tap & 1) ? wfB : wfA;
        unsigned* nxt = (tap & 1) ? wfA : wfB;
        if (tap + 1 < 9) {
            for (int i = tid; i < C3_WF; i += 256) {
                int h = i & 1, ln = (i >> 1) & 31, j = (i >> 6) & 7, ks = (i >> 9) & 3, half = i >> 11;
                int tt = ln & 3, gg = ln >> 2;
                int k = ks * 16 + 2 * tt + 8 * h;
                int oc = half * 64 + j * 8 + gg;
                nxt[i] = packh2(w3[oc * 576 + k * 9 + tap + 1],
                                w3[oc * 576 + (k + 1) * 9 + tap + 1]);
            }
        }
        int ky = tap / 3, kx = tap - ky * 3;
        int shift = (ky - 1) * 15 + (kx - 1);
        bool val[8]; int aoff[8];
        #pragma unroll
        for (int i = 0; i < 8; i++) {
            val[i] = (prow[i] < 225) && ((unsigned)(ppy[i] + ky - 1) < 15u)
                                     && ((unsigned)(ppx[i] + kx - 1) < 15u);
            aoff[i] = (prow[i] + shift) * 34 + 2 * t;
        }
        #pragma unroll
        for (int ks = 0; ks < 4; ks++) {
            int k0 = ks * 8;
            uint2 B[8];
            #pragma unroll
            for (int j = 0; j < 8; j++)
                B[j] = *(const uint2*)&cur[ochalf * 2048 + ((ks * 8 + j) * 32 + lane) * 2];
            #pragma unroll
            for (int mt = 0; mt < 4; mt++) {
                uint2 A0 = make_uint2(0u, 0u), A1 = make_uint2(0u, 0u);
                if (val[2 * mt])     A0 = *(const uint2*)&sIn[aoff[2 * mt] + k0];
                if (val[2 * mt + 1]) A1 = *(const uint2*)&sIn[aoff[2 * mt + 1] + k0];
                #pragma unroll
                for (int j = 0; j < 8; j++)
                    mma_f16(acc[mt][j][0], acc[mt][j][1], acc[mt][j][2], acc[mt][j][3],
                            A0.x, A1.x, A0.y, A1.y, B[j].x, B[j].y);
            }
        }
        __syncthreads();
    }

    #pragma unroll
    for (int j = 0; j < 8; j++) {
        int oc = ochalf * 64 + j * 8 + 2 * t;
        float2 bb = *(const float2*)&b3[oc];
        #pragma unroll
        for (int mt = 0; mt < 4; mt++) {
            int plo = prow[mt * 2], phi = prow[mt * 2 + 1];
            if (plo < 225) {
                float2 o;
                o.x = fmaxf(acc[mt][j][0] + bb.x, 0.f);
                o.y = fmaxf(acc[mt][j][1] + bb.y, 0.f);
                *(float2*)&g_c3[((size_t)b * 225 + plo) * 128 + oc] = o;
            }
            if (phi < 225) {
                float2 o;
                o.x = fmaxf(acc[mt][j][2] + bb.x, 0.f);
                o.y = fmaxf(acc[mt][j][3] + bb.y, 0.f);
                *(float2*)&g_c3[((size_t)b * 225 + phi) * 128 + oc] = o;
            }
        }
    }
}

// ---------------------------------------------------------------------------
// Pool3 + mean
// ---------------------------------------------------------------------------
__global__ void k_avg() {
    int idx = blockIdx.x * 256 + threadIdx.x;
    int oc = idx & 127; int b = idx >> 7;
    const float* ip = g_c3 + (size_t)b * 225 * 128 + oc;
    float s = 0.f;
    #pragma unroll
    for (int py = 0; py < 7; py++)
        #pragma unroll
        for (int px = 0; px < 7; px++) {
            const float* w = ip + ((2 * py) * 15 + 2 * px) * 128;
            float m = fmaxf(fmaxf(w[0], w[128]), fmaxf(w[15 * 128], w[16 * 128]));
            s += m;
        }
    g_avg[idx] = s * (1.f / 49.f);
}

__global__ void k_fc(const float* __restrict__ fw1, const float* __restrict__ fb1,
                     const float* __restrict__ fw2, const float* __restrict__ fb2,
                     float* __restrict__ out) {
    int b = blockIdx.x;
    int tid = threadIdx.x;
    __shared__ float sa[128], sh[128];
    sa[tid] = g_avg[b * 128 + tid];
    __syncthreads();
    float s = fb1[tid];
    const float* wr = fw1 + tid * 128;
    #pragma unroll 8
    for (int j = 0; j < 128; j++) s += wr[j] * sa[j];
    sh[tid] = s > 0.f ? s : 0.f;
    __syncthreads();
    if (tid < 5) {
        float o = fb2[tid];
        const float* wr2 = fw2 + tid * 128;
        #pragma unroll 8
        for (int j = 0; j < 128; j++) o += wr2[j] * sh[j];
        out[b * 5 + tid] = o;
    }
}

// ---------------------------------------------------------------------------
extern "C" void kernel_launch(void* const* d_in, const int* in_sizes, int n_in,
                              void* d_out, int out_size) {
    const int*   x   = (const int*)  d_in[0];
    const float* w1  = (const float*)d_in[1];
    const float* b1  = (const float*)d_in[2];
    const float* w2  = (const float*)d_in[3];
    const float* b2  = (const float*)d_in[4];
    const float* w3  = (const float*)d_in[5];
    const float* b3  = (const float*)d_in[6];
    const float* fw1 = (const float*)d_in[7];
    const float* fb1 = (const float*)d_in[8];
    const float* fw2 = (const float*)d_in[9];
    const float* fb2 = (const float*)d_in[10];
    float* out = (float*)d_out;

    cudaFuncSetAttribute(k_conv2_mma, cudaFuncAttributeMaxDynamicSharedMemorySize, C2_SMEM);
    cudaFuncSetAttribute(k_conv3_mma, cudaFuncAttributeMaxDynamicSharedMemorySize, C3_SMEM);

    k_raster_nz<<<NIMG, 256>>>(x);
    k_zero_c1<<<65536, 256>>>();
    k_scatter1<<<NIMG, 256>>>(w1);
    k_pool1<<<(NB * 961 * 32) / 256, 256>>>(b1);
    k_conv2_mma<<<dim3(NB, 2), 256, C2_SMEM>>>(w2, b2);
    k_pool2<<<(NB * 225 * 64) / 256, 256>>>();
    k_conv3_mma<<<NB, 256, C3_SMEM>>>(w3, b3);
    k_avg<<<(NB * 128) / 256, 256>>>();
    k_fc<<<NB, 128>>>(fw1, fb1, fw2, fb2, out);
}

// round 8
// speedup vs baseline: 6.7906x; 1.4020x over previous
#include <cuda_runtime.h>
#include <cuda_bf16.h>
#include <cuda_fp16.h>
#include <math_constants.h>

// ---------------------------------------------------------------------------
//   x [512,4,10,2] i32 -> nonzero list
//   conv1 7x7 s2 p3 4->32 : SPARSE scatter-add into c1 [512,64,64,32] NHWC
//   pool1 3x3 s2 (+bias+relu)        -> p1 [512,961,32]
//   conv2 5x5 s1 p2 32->64 (+relu)   -> c2 [512,961,64]   (fp16 mma, f32 accum)
//   pool2 2x2 s2                     -> p2 [512,225,64]
//   conv3 3x3 s1 p1 64->128 (+relu)  -> c3 [512,225,128]  (fp16 mma, f32 accum)
//   pool 2x2 s2 + mean               -> avg [512,128]
//   fc 128->128 relu -> 5            -> out [512,5]
//
// Weights pre-packed (k_prep2/k_prep3) into fragment-order f16x2; conv
// mainloops are pure LDS+HMMA with one barrier after staging.
// NOTE: weight smem regions are padded to 16B alignment (uint4 copy).
//
// mma.m16n8k16.f16 fragment maps (g=lane>>2, t=lane&3), f16x2 regs:
//   A: a0=(g, 2t:2t+1) a1=(g+8, 2t:2t+1) a2=(g, 2t+8:2t+9) a3=(g+8, 2t+8:2t+9)
//   B: b0=B[2t:2t+1][g] b1=B[2t+8:2t+9][g]
//   C: c0=(g,2t) c1=(g,2t+1) c2=(g+8,2t) c3=(g+8,2t+1)
// Channel pairs (uint = f16x2 of ch 2q,2q+1) permuted within each 16-channel
// chunk: (0,4),(1,5),(2,6),(3,7) so thread t's uint2 at pair-offset 2t gives
// k (2t,2t+1) and (2t+8,2t+9).
// ---------------------------------------------------------------------------

#define NB 512
#define NIMG (NB * 4)

__device__ float g_c1 [NB * 64 * 64 * 32];
__device__ float g_p1 [NB * 961 * 32];
__device__ float g_c2 [NB * 961 * 64];
__device__ float g_p2 [NB * 225 * 64];
__device__ float g_c3 [NB * 225 * 128];
__device__ float g_avg[NB * 128];
__device__ int            g_nzcnt [NIMG];
__device__ unsigned short g_nzlist[NIMG * 256];
__device__ __align__(16) unsigned g_w2f[25 * 1024];   // conv2 weights, fragment order
__device__ __align__(16) unsigned g_w3f[9 * 4096];    // conv3 weights, fragment order

__device__ __forceinline__ unsigned packh2(float a, float b) {
    __half2 h = __floats2half2_rn(a, b);
    return *(unsigned*)&h;
}

__device__ __forceinline__ void mma_f16(float& c0, float& c1, float& c2, float& c3,
                                        unsigned a0, unsigned a1, unsigned a2, unsigned a3,
                                        unsigned b0, unsigned b1) {
    asm volatile("mma.sync.aligned.m16n8k16.row.col.f32.f16.f16.f32 "
                 "{%0,%1,%2,%3},{%4,%5,%6,%7},{%8,%9},{%0,%1,%2,%3};"
                 : "+f"(c0), "+f"(c1), "+f"(c2), "+f"(c3)
                 : "r"(a0), "r"(a1), "r"(a2), "r"(a3), "r"(b0), "r"(b1));
}

// ---------------------------------------------------------------------------
// Weight pre-pack kernels (tiny; once per launch)
// ---------------------------------------------------------------------------
__global__ void k_prep2(const float* __restrict__ w2) {
    int i = blockIdx.x * 256 + threadIdx.x;          // 25600
    if (i >= 25600) return;
    int i2 = i & 1023, tap = i >> 10;
    int h = i2 & 1, ln = (i2 >> 1) & 31, j = (i2 >> 6) & 7, ks = i2 >> 9;
    int tt = ln & 3, gg = ln >> 2;
    int k = ks * 16 + 2 * tt + 8 * h;
    int n = j * 8 + gg;
    g_w2f[i] = packh2(w2[n * 800 + k * 25 + tap], w2[n * 800 + (k + 1) * 25 + tap]);
}

__global__ void k_prep3(const float* __restrict__ w3) {
    int i = blockIdx.x * 256 + threadIdx.x;          // 36864
    if (i >= 36864) return;
    int i2 = i & 4095, tap = i >> 12;
    int h = i2 & 1, ln = (i2 >> 1) & 31, j = (i2 >> 6) & 7, ks = (i2 >> 9) & 3, half = i2 >> 11;
    int tt = ln & 3, gg = ln >> 2;
    int k = ks * 16 + 2 * tt + 8 * h;
    int oc = half * 64 + j * 8 + gg;
    g_w3f[i] = packh2(w3[oc * 576 + k * 9 + tap], w3[oc * 576 + (k + 1) * 9 + tap]);
}

// ---------------------------------------------------------------------------
// Rasterize to nonzero list. Entry: p | code<<14; code 0=0.5, 1=1.0, 2=-1.0
// ---------------------------------------------------------------------------
__global__ void k_raster_nz(const int* __restrict__ x) {
    int img = blockIdx.x;
    __shared__ int ax[9], ay[9];
    __shared__ int sdX, sloX, shiX, sloY, shiY;
    __shared__ int sCnt;
    __shared__ unsigned short sList[256];
    int tid = threadIdx.x;
    if (tid < 9) {
        int vx = x[img * 20 + tid * 2 + 0];
        int vy = x[img * 20 + tid * 2 + 1];
        ax[tid] = ((vx + 64) % 127 + 127) % 127;
        ay[tid] = ((64 - vy) % 127 + 127) % 127;
    }
    if (tid == 9) {
        int vx = x[img * 20 + 18];
        int vy = x[img * 20 + 19];
        int dX = 64 + vx, dY = 64 - vy;
        sdX = dX;
        sloX = (dX >= 64) ? 64 : dX + 1;
        shiX = (dX >= 64) ? dX - 1 : 64;
        sloY = (dY >= 64) ? 64 : dY + 1;
        shiY = (dY >= 64) ? dY - 1 : 64;
    }
    if (tid == 10) sCnt = 0;
    __syncthreads();
    for (int p = tid; p < 16384; p += blockDim.x) {
        int y = p >> 7, xx = p & 127;
        float val = 0.f;
        if (y == 64 && xx >= sloX && xx <= shiX) val = -1.f;
        if (xx == sdX && y >= sloY && y <= shiY) val = -1.f;
        if (y >= 63 && y <= 65 && xx >= 63 && xx <= 65)
            val = (y == 64 && xx == 64) ? 1.f : 0.5f;
        #pragma unroll
        for (int k = 0; k < 9; k++) {
            int dy = y - ay[k], dx = xx - ax[k];
            if (dy >= -1 && dy <= 1 && dx >= -1 && dx <= 1)
                val = (dy == 0 && dx == 0) ? 1.f : 0.5f;
        }
        if (val != 0.f) {
            int pos = atomicAdd(&sCnt, 1);
            if (pos < 256) {
                int code = (val == 0.5f) ? 0 : ((val == 1.f) ? 1 : 2);
                sList[pos] = (unsigned short)(p | (code << 14));
            }
        }
    }
    __syncthreads();
    int cnt = sCnt < 256 ? sCnt : 256;
    if (tid == 0) g_nzcnt[img] = cnt;
    for (int i = tid; i < cnt; i += blockDim.x)
        g_nzlist[img * 256 + i] = sList[i];
}

__global__ void k_zero_c1() {
    int i = blockIdx.x * 256 + threadIdx.x;
    ((float4*)g_c1)[i] = make_float4(0.f, 0.f, 0.f, 0.f);
}

// ---------------------------------------------------------------------------
// Sparse conv1: block per (b,ci). Warp = one nonzero pixel, lanes = 32 oc.
// ---------------------------------------------------------------------------
__global__ void k_scatter1(const float* __restrict__ w1) {
    int img = blockIdx.x;
    int b = img >> 2, ci = img & 3;
    __shared__ float sW[49 * 32];
    __shared__ unsigned short sList[256];
    __shared__ int sCnt;
    int tid = threadIdx.x;
    for (int i = tid; i < 49 * 32; i += 256) {
        int oc = i & 31; int r = i >> 5;
        int ky = r / 7, kx = r % 7;
        sW[i] = w1[((oc * 4 + ci) * 7 + ky) * 7 + kx];
    }
    if (tid == 0) sCnt = g_nzcnt[img];
    __syncthreads();
    int cnt = sCnt;
    for (int i = tid; i < cnt; i += 256) sList[i] = g_nzlist[img * 256 + i];
    __syncthreads();
    int warp = tid >> 5, lane = tid & 31;
    for (int e = warp; e < cnt; e += 8) {
        int ent = sList[e];
        int p = ent & 16383, code = ent >> 14;
        float v = (code == 0) ? 0.5f : ((code == 1) ? 1.0f : -1.0f);
        int iy = p >> 7, ix = p & 127;
        #pragma unroll
        for (int ky = 0; ky < 7; ky++) {
            int t = iy + 3 - ky;
            if (t < 0 || t >= 128 || (t & 1)) continue;
            int oy = t >> 1;
            #pragma unroll
            for (int kx = 0; kx < 7; kx++) {
                int u = ix + 3 - kx;
                if (u < 0 || u >= 128 || (u & 1)) continue;
                int ox = u >> 1;
                atomicAdd(&g_c1[((b * 64 + oy) * 64 + ox) * 32 + lane],
                          v * sW[(ky * 7 + kx) * 32 + lane]);
            }
        }
    }
}

// ---------------------------------------------------------------------------
// Pool1 3x3 s2 + bias + relu
// ---------------------------------------------------------------------------
__global__ void k_pool1(const float* __restrict__ b1) {
    int idx = blockIdx.x * 256 + threadIdx.x;
    int oc = idx & 31; int t = idx >> 5;
    int px = t % 31; int py = (t / 31) % 31; int b = t / 961;
    const float* ip = g_c1 + ((size_t)(b * 64 + 2 * py) * 64 + 2 * px) * 32 + oc;
    float m = -CUDART_INF_F;
    #pragma unroll
    for (int dy = 0; dy < 3; dy++)
        #pragma unroll
        for (int dx = 0; dx < 3; dx++)
            m = fmaxf(m, ip[(dy * 64 + dx) * 32]);
    float v = m + b1[oc];
    g_p1[idx] = v > 0.f ? v : 0.f;
}

// ---------------------------------------------------------------------------
// Conv2 via fp16 mma. grid (512, 2), block 256 (8 warps).
// Warp: 64 px (4 m16 tiles) x 64 oc (8 n8 tiles). K = 32 ci x 25 taps (2 ks).
// ALL 25 taps' weights staged in smem once; mainloop barrier-free.
// ---------------------------------------------------------------------------
#define C2_SIN   (961 * 18)                        // 17298 uints
#define C2_WOFF  17300                             // wf offset, 16B aligned
#define C2_WF    (25 * 1024)                       // 25600 uints
#define C2_SMEM  ((C2_WOFF + C2_WF) * 4)           // 171600 B

extern __shared__ unsigned smem_u[];

__global__ __launch_bounds__(256, 1) void k_conv2_mma(const float* __restrict__ b2) {
    unsigned* sIn = smem_u;
    unsigned* wf  = smem_u + C2_WOFF;
    int b = blockIdx.x;
    int tid = threadIdx.x;
    int warp = tid >> 5, lane = tid & 31;
    int g = lane >> 2, t = lane & 3;

    const float* src = g_p1 + (size_t)b * 30752;
    for (int i = tid; i < 961 * 16; i += 256) {
        int p = i >> 4, u = i & 15;
        int chunk = u >> 3, q = u & 7;
        int pos = 2 * (q & 3) + (q >> 2);
        float2 v = *(const float2*)&src[p * 32 + chunk * 16 + 2 * q];
        sIn[p * 18 + chunk * 8 + pos] = packh2(v.x, v.y);
    }
    {
        const uint4* ws = (const uint4*)g_w2f;
        uint4* wd = (uint4*)wf;
        for (int i = tid; i < C2_WF / 4; i += 256) wd[i] = ws[i];
    }
    __syncthreads();

    int p0 = blockIdx.y * 512 + warp * 64;
    int prow[8], ppy[8], ppx[8];
    #pragma unroll
    for (int mt = 0; mt < 4; mt++)
        #pragma unroll
        for (int h = 0; h < 2; h++) {
            int i = mt * 2 + h;
            int p = p0 + mt * 16 + g + h * 8;
            prow[i] = p; ppy[i] = p / 31; ppx[i] = p - ppy[i] * 31;
        }

    float acc[4][8][4];
    #pragma unroll
    for (int mt = 0; mt < 4; mt++)
        #pragma unroll
        for (int j = 0; j < 8; j++)
            #pragma unroll
            for (int q = 0; q < 4; q++) acc[mt][j][q] = 0.f;

    #pragma unroll 1
    for (int tap = 0; tap < 25; tap++) {
        const unsigned* cur = wf + tap * 1024;
        int ky = tap / 5, kx = tap - ky * 5;
        int shift = (ky - 2) * 31 + (kx - 2);
        bool val[8]; int aoff[8];
        #pragma unroll
        for (int i = 0; i < 8; i++) {
            val[i] = (prow[i] < 961) && ((unsigned)(ppy[i] + ky - 2) < 31u)
                                     && ((unsigned)(ppx[i] + kx - 2) < 31u);
            aoff[i] = (prow[i] + shift) * 18 + 2 * t;
        }
        #pragma unroll
        for (int ks = 0; ks < 2; ks++) {
            int k0 = ks * 8;
            uint2 B[8];
            #pragma unroll
            for (int j = 0; j < 8; j++)
                B[j] = *(const uint2*)&cur[((ks * 8 + j) * 32 + lane) * 2];
            #pragma unroll
            for (int mt = 0; mt < 4; mt++) {
                uint2 A0 = make_uint2(0u, 0u), A1 = make_uint2(0u, 0u);
                if (val[2 * mt])     A0 = *(const uint2*)&sIn[aoff[2 * mt] + k0];
                if (val[2 * mt + 1]) A1 = *(const uint2*)&sIn[aoff[2 * mt + 1] + k0];
                #pragma unroll
                for (int j = 0; j < 8; j++)
                    mma_f16(acc[mt][j][0], acc[mt][j][1], acc[mt][j][2], acc[mt][j][3],
                            A0.x, A1.x, A0.y, A1.y, B[j].x, B[j].y);
            }
        }
    }

    #pragma unroll
    for (int j = 0; j < 8; j++) {
        int oc = j * 8 + 2 * t;
        float2 bb = *(const float2*)&b2[oc];
        #pragma unroll
        for (int mt = 0; mt < 4; mt++) {
            int plo = prow[mt * 2], phi = prow[mt * 2 + 1];
            if (plo < 961) {
                float2 o;
                o.x = fmaxf(acc[mt][j][0] + bb.x, 0.f);
                o.y = fmaxf(acc[mt][j][1] + bb.y, 0.f);
                *(float2*)&g_c2[((size_t)b * 961 + plo) * 64 + oc] = o;
            }
            if (phi < 961) {
                float2 o;
                o.x = fmaxf(acc[mt][j][2] + bb.x, 0.f);
                o.y = fmaxf(acc[mt][j][3] + bb.y, 0.f);
                *(float2*)&g_c2[((size_t)b * 961 + phi) * 64 + oc] = o;
            }
        }
    }
}

// ---------------------------------------------------------------------------
// Pool2 2x2 s2
// ---------------------------------------------------------------------------
__global__ void k_pool2() {
    int idx = blockIdx.x * 256 + threadIdx.x;
    int oc = idx & 63; int t = idx >> 6;
    int px = t % 15; int py = (t / 15) % 15; int b = t / 225;
    const float* ip = g_c2 + ((size_t)(b * 31 + 2 * py) * 31 + 2 * px) * 64 + oc;
    float m = fmaxf(fmaxf(ip[0], ip[64]), fmaxf(ip[31 * 64], ip[32 * 64]));
    g_p2[idx] = m;
}

// ---------------------------------------------------------------------------
// Conv3 via fp16 mma. grid (512), block 256.
// Warp (w): px quarter = (w&3)*64, oc half = (w>>2)*64. K = 64 ci x 9 taps (4 ks).
// ALL 9 taps' weights staged in smem once; mainloop barrier-free.
// ---------------------------------------------------------------------------
#define C3_SIN   (225 * 34)                        // 7650 uints
#define C3_WOFF  7652                              // wf offset, 16B aligned
#define C3_WF    (9 * 4096)                        // 36864 uints
#define C3_SMEM  ((C3_WOFF + C3_WF) * 4)           // 178064 B

__global__ __launch_bounds__(256, 1) void k_conv3_mma(const float* __restrict__ b3) {
    unsigned* sIn = smem_u;
    unsigned* wf  = smem_u + C3_WOFF;
    int b = blockIdx.x;
    int tid = threadIdx.x;
    int warp = tid >> 5, lane = tid & 31;
    int g = lane >> 2, t = lane & 3;

    const float* src = g_p2 + (size_t)b * 14400;
    for (int i = tid; i < 225 * 32; i += 256) {
        int p = i >> 5, u = i & 31;
        int chunk = u >> 3, q = u & 7;
        int pos = 2 * (q & 3) + (q >> 2);
        float2 v = *(const float2*)&src[p * 64 + chunk * 16 + 2 * q];
        sIn[p * 34 + chunk * 8 + pos] = packh2(v.x, v.y);
    }
    {
        const uint4* ws = (const uint4*)g_w3f;
        uint4* wd = (uint4*)wf;
        for (int i = tid; i < C3_WF / 4; i += 256) wd[i] = ws[i];
    }
    __syncthreads();

    int p0 = (warp & 3) * 64;
    int ochalf = warp >> 2;
    int prow[8], ppy[8], ppx[8];
    #pragma unroll
    for (int mt = 0; mt < 4; mt++)
        #pragma unroll
        for (int h = 0; h < 2; h++) {
            int i = mt * 2 + h;
            int p = p0 + mt * 16 + g + h * 8;
            prow[i] = p; ppy[i] = p / 15; ppx[i] = p - ppy[i] * 15;
        }

    float acc[4][8][4];
    #pragma unroll
    for (int mt = 0; mt < 4; mt++)
        #pragma unroll
        for (int j = 0; j < 8; j++)
            #pragma unroll
            for (int q = 0; q < 4; q++) acc[mt][j][q] = 0.f;

    #pragma unroll 1
    for (int tap = 0; tap < 9; tap++) {
        const unsigned* cur = wf + tap * 4096 + ochalf * 2048;
        int ky = tap / 3, kx = tap - ky * 3;
        int shift = (ky - 1) * 15 + (kx - 1);
        bool val[8]; int aoff[8];
        #pragma unroll
        for (int i = 0; i < 8; i++) {
            val[i] = (prow[i] < 225) && ((unsigned)(ppy[i] + ky - 1) < 15u)
                                     && ((unsigned)(ppx[i] + kx - 1) < 15u);
            aoff[i] = (prow[i] + shift) * 34 + 2 * t;
        }
        #pragma unroll
        for (int ks = 0; ks < 4; ks++) {
            int k0 = ks * 8;
            uint2 B[8];
            #pragma unroll
            for (int j = 0; j < 8; j++)
                B[j] = *(const uint2*)&cur[((ks * 8 + j) * 32 + lane) * 2];
            #pragma unroll
            for (int mt = 0; mt < 4; mt++) {
                uint2 A0 = make_uint2(0u, 0u), A1 = make_uint2(0u, 0u);
                if (val[2 * mt])     A0 = *(const uint2*)&sIn[aoff[2 * mt] + k0];
                if (val[2 * mt + 1]) A1 = *(const uint2*)&sIn[aoff[2 * mt + 1] + k0];
                #pragma unroll
                for (int j = 0; j < 8; j++)
                    mma_f16(acc[mt][j][0], acc[mt][j][1], acc[mt][j][2], acc[mt][j][3],
                            A0.x, A1.x, A0.y, A1.y, B[j].x, B[j].y);
            }
        }
    }

    #pragma unroll
    for (int j = 0; j < 8; j++) {
        int oc = ochalf * 64 + j * 8 + 2 * t;
        float2 bb = *(const float2*)&b3[oc];
        #pragma unroll
        for (int mt = 0; mt < 4; mt++) {
            int plo = prow[mt * 2], phi = prow[mt * 2 + 1];
            if (plo < 225) {
                float2 o;
                o.x = fmaxf(acc[mt][j][0] + bb.x, 0.f);
                o.y = fmaxf(acc[mt][j][1] + bb.y, 0.f);
                *(float2*)&g_c3[((size_t)b * 225 + plo) * 128 + oc] = o;
            }
            if (phi < 225) {
                float2 o;
                o.x = fmaxf(acc[mt][j][2] + bb.x, 0.f);
                o.y = fmaxf(acc[mt][j][3] + bb.y, 0.f);
                *(float2*)&g_c3[((size_t)b * 225 + phi) * 128 + oc] = o;
            }
        }
    }
}

// ---------------------------------------------------------------------------
// Pool3 + mean
// ---------------------------------------------------------------------------
__global__ void k_avg() {
    int idx = blockIdx.x * 256 + threadIdx.x;
    int oc = idx & 127; int b = idx >> 7;
    const float* ip = g_c3 + (size_t)b * 225 * 128 + oc;
    float s = 0.f;
    #pragma unroll
    for (int py = 0; py < 7; py++)
        #pragma unroll
        for (int px = 0; px < 7; px++) {
            const float* w = ip + ((2 * py) * 15 + 2 * px) * 128;
            float m = fmaxf(fmaxf(w[0], w[128]), fmaxf(w[15 * 128], w[16 * 128]));
            s += m;
        }
    g_avg[idx] = s * (1.f / 49.f);
}

__global__ void k_fc(const float* __restrict__ fw1, const float* __restrict__ fb1,
                     const float* __restrict__ fw2, const float* __restrict__ fb2,
                     float* __restrict__ out) {
    int b = blockIdx.x;
    int tid = threadIdx.x;
    __shared__ float sa[128], sh[128];
    sa[tid] = g_avg[b * 128 + tid];
    __syncthreads();
    float s = fb1[tid];
    const float* wr = fw1 + tid * 128;
    #pragma unroll 8
    for (int j = 0; j < 128; j++) s += wr[j] * sa[j];
    sh[tid] = s > 0.f ? s : 0.f;
    __syncthreads();
    if (tid < 5) {
        float o = fb2[tid];
        const float* wr2 = fw2 + tid * 128;
        #pragma unroll 8
        for (int j = 0; j < 128; j++) o += wr2[j] * sh[j];
        out[b * 5 + tid] = o;
    }
}

// ---------------------------------------------------------------------------
extern "C" void kernel_launch(void* const* d_in, const int* in_sizes, int n_in,
                              void* d_out, int out_size) {
    const int*   x   = (const int*)  d_in[0];
    const float* w1  = (const float*)d_in[1];
    const float* b1  = (const float*)d_in[2];
    const float* w2  = (const float*)d_in[3];
    const float* b2  = (const float*)d_in[4];
    const float* w3  = (const float*)d_in[5];
    const float* b3  = (const float*)d_in[6];
    const float* fw1 = (const float*)d_in[7];
    const float* fb1 = (const float*)d_in[8];
    const float* fw2 = (const float*)d_in[9];
    const float* fb2 = (const float*)d_in[10];
    float* out = (float*)d_out;

    cudaFuncSetAttribute(k_conv2_mma, cudaFuncAttributeMaxDynamicSharedMemorySize, C2_SMEM);
    cudaFuncSetAttribute(k_conv3_mma, cudaFuncAttributeMaxDynamicSharedMemorySize, C3_SMEM);

    k_prep2<<<100, 256>>>(w2);
    k_prep3<<<144, 256>>>(w3);
    k_raster_nz<<<NIMG, 256>>>(x);
    k_zero_c1<<<65536, 256>>>();
    k_scatter1<<<NIMG, 256>>>(w1);
    k_pool1<<<(NB * 961 * 32) / 256, 256>>>(b1);
    k_conv2_mma<<<dim3(NB, 2), 256, C2_SMEM>>>(b2);
    k_pool2<<<(NB * 225 * 64) / 256, 256>>>();
    k_conv3_mma<<<NB, 256, C3_SMEM>>>(b3);
    k_avg<<<(NB * 128) / 256, 256>>>();
    k_fc<<<NB, 128>>>(fw1, fb1, fw2, fb2, out);
}